// round 1
// baseline (speedup 1.0000x reference)
#include <cuda_runtime.h>
#include <math.h>

// Problem constants
#define NB 4
#define LQ 8192
#define SSEQ 8192
#define CC 256
#define HH 8
#define DD 32
#define MTOT (NB*LQ)     // 32768 query rows
#define MSRC (NB*SSEQ)   // 32768 source rows
#define CHUNKS 64        // S/128 per batch
#define KVSZ (HH*DD*DD)  // 8192 per batch

// Scratch (device globals: no allocation allowed)
__device__ float g_query[MTOT*CC];
__device__ float g_key[MSRC*CC];
__device__ float g_value[MSRC*CC];
__device__ float g_Kpart[NB*CHUNKS*CC];
__device__ float g_KVpart[(size_t)NB*CHUNKS*KVSZ];
__device__ float g_Ksum[NB*CC];
__device__ float g_KV[NB*KVSZ];
__device__ float g_queried[MTOT*CC];
__device__ float g_msg[MTOT*CC];
__device__ float g_m1[MTOT*CC];
__device__ float g_h[(size_t)MTOT*2*CC];
__device__ float g_h2[MTOT*CC];

// ---------------------------------------------------------------------------
// Classic 128x128x8 SGEMM, Y[m,n] = act( sum_k Ain[m,k] * W[n,k] )
// Ain = A for k < Ksplit else A2 (k - Ksplit). Both sources have row stride lda.
// W is [Nn, K] row-major (stride K). Y is [M, Nn] row-major.
// ---------------------------------------------------------------------------
__global__ void __launch_bounds__(256) sgemm_nt(
    const float* __restrict__ A, const float* __restrict__ A2, int Ksplit, int lda,
    const float* __restrict__ W, float* __restrict__ Y,
    int Nn, int K, int relu)
{
    __shared__ float As[8][128];
    __shared__ float Bs[8][128];
    const int tid = threadIdx.x;
    const int bm = blockIdx.y * 128;
    const int bn = blockIdx.x * 128;
    const int lr = tid >> 1;         // 0..127
    const int lc = (tid & 1) << 2;   // 0 or 4
    const int tx = tid & 15;
    const int ty = tid >> 4;

    float acc[8][8];
#pragma unroll
    for (int i = 0; i < 8; i++)
#pragma unroll
        for (int j = 0; j < 8; j++) acc[i][j] = 0.f;

    for (int k0 = 0; k0 < K; k0 += 8) {
        const float* Ap = (k0 < Ksplit)
            ? (A  + (size_t)(bm + lr) * lda + k0 + lc)
            : (A2 + (size_t)(bm + lr) * lda + (k0 - Ksplit) + lc);
        float4 av = *(const float4*)Ap;
        float4 bv = *(const float4*)(W + (size_t)(bn + lr) * K + k0 + lc);
        As[lc+0][lr] = av.x; As[lc+1][lr] = av.y; As[lc+2][lr] = av.z; As[lc+3][lr] = av.w;
        Bs[lc+0][lr] = bv.x; Bs[lc+1][lr] = bv.y; Bs[lc+2][lr] = bv.z; Bs[lc+3][lr] = bv.w;
        __syncthreads();
#pragma unroll
        for (int k = 0; k < 8; k++) {
            float4 a0 = *(const float4*)&As[k][ty*8];
            float4 a1 = *(const float4*)&As[k][ty*8+4];
            float4 b0 = *(const float4*)&Bs[k][tx*8];
            float4 b1 = *(const float4*)&Bs[k][tx*8+4];
            float af[8] = {a0.x,a0.y,a0.z,a0.w,a1.x,a1.y,a1.z,a1.w};
            float bf[8] = {b0.x,b0.y,b0.z,b0.w,b1.x,b1.y,b1.z,b1.w};
#pragma unroll
            for (int i = 0; i < 8; i++)
#pragma unroll
                for (int j = 0; j < 8; j++)
                    acc[i][j] = fmaf(af[i], bf[j], acc[i][j]);
        }
        __syncthreads();
    }
#pragma unroll
    for (int i = 0; i < 8; i++) {
        size_t ro = (size_t)(bm + ty*8 + i) * Nn + bn + tx*8;
#pragma unroll
        for (int j = 0; j < 8; j++) {
            float v = acc[i][j];
            if (relu) v = fmaxf(v, 0.f);
            Y[ro + j] = v;
        }
    }
}

// ---------------------------------------------------------------------------
// Stage B: per source row — K = (elu(key)+1)*mask, K_pos = rotary(key)*mask,
// V = rotary(value)*mask.  Accumulate per-chunk partials:
//   Kpart[n,chunk,c]  = sum_s K[c]
//   KVpart[n,chunk,h,d,v] = sum_s K_pos[h,d] * V[h,v]
// 128 rows per block; deterministic (no atomics).
// ---------------------------------------------------------------------------
__global__ void __launch_bounds__(256) stageB_kernel(
    const float* __restrict__ key, const float* __restrict__ value,
    const float* __restrict__ spe, const float* __restrict__ smask,
    float* __restrict__ Kpart, float* __restrict__ KVpart)
{
    const int n = blockIdx.x / CHUNKS;
    const int chunk = blockIdx.x % CHUNKS;
    const int s0 = chunk * 128;
    const int c = threadIdx.x;
    const int h = c >> 5, lane = c & 31;
    const int d_base = (lane & 7) * 4;   // 8 d-blocks of 4
    const int v_base = (lane >> 3) * 8;  // 4 v-blocks of 8

    __shared__ float sKp[256], sV[256];
    float accKV[4][8];
#pragma unroll
    for (int i = 0; i < 4; i++)
#pragma unroll
        for (int j = 0; j < 8; j++) accKV[i][j] = 0.f;
    float accKs = 0.f;

    const size_t base = ((size_t)n * SSEQ + s0) * CC;
    for (int r = 0; r < 128; r++) {
        size_t row = base + (size_t)r * CC;
        float kc = key[row + c];
        float kp = key[row + (c ^ 1)];
        float vc = value[row + c];
        float vp = value[row + (c ^ 1)];
        float cs = spe[(row + c) * 2 + 0];
        float sn = spe[(row + c) * 2 + 1];
        float m  = smask[(size_t)n * SSEQ + s0 + r];
        float k2 = (c & 1) ? kp : -kp;   // rotary partner with sign
        float v2 = (c & 1) ? vp : -vp;
        float Kf   = (kc > 0.f ? kc + 1.f : expf(kc)) * m;
        float Kpos = (kc * cs + k2 * sn) * m;
        float Vr   = (vc * cs + v2 * sn) * m;
        accKs += Kf;
        sKp[c] = Kpos; sV[c] = Vr;
        __syncthreads();
        float a[4], b[8];
#pragma unroll
        for (int i = 0; i < 4; i++) a[i] = sKp[h*32 + d_base + i];
#pragma unroll
        for (int j = 0; j < 8; j++) b[j] = sV[h*32 + v_base + j];
#pragma unroll
        for (int i = 0; i < 4; i++)
#pragma unroll
            for (int j = 0; j < 8; j++)
                accKV[i][j] = fmaf(a[i], b[j], accKV[i][j]);
        __syncthreads();
    }
    Kpart[(size_t)(n*CHUNKS + chunk)*CC + c] = accKs;
    size_t kvb = (size_t)(n*CHUNKS + chunk)*KVSZ + h*1024;
#pragma unroll
    for (int i = 0; i < 4; i++)
#pragma unroll
        for (int j = 0; j < 8; j++)
            KVpart[kvb + (d_base+i)*32 + v_base + j] = accKV[i][j];
}

// Fixed-order reduction of chunk partials -> Ksum, KV (deterministic)
__global__ void __launch_bounds__(256) reduce_parts(
    const float* __restrict__ Kpart, const float* __restrict__ KVpart,
    float* __restrict__ Ksum, float* __restrict__ KV)
{
    int idx = blockIdx.x * 256 + threadIdx.x;
    if (idx < NB*CC) {
        int n = idx / CC, c = idx % CC;
        float s = 0.f;
        for (int ch = 0; ch < CHUNKS; ch++)
            s += Kpart[(size_t)(n*CHUNKS + ch)*CC + c];
        Ksum[idx] = s;
        return;
    }
    int kidx = idx - NB*CC;
    if (kidx < NB*KVSZ) {
        int n = kidx / KVSZ, e = kidx % KVSZ;
        float s = 0.f;
        for (int ch = 0; ch < CHUNKS; ch++)
            s += KVpart[(size_t)(n*CHUNKS + ch)*KVSZ + e];
        KV[kidx] = s;
    }
}

// ---------------------------------------------------------------------------
// Stage C: per query row — Q = (elu(query)+1)*mask, Q_pos = rotary(query)*mask,
// Z = 1/(Q·Ksum + eps) per head (warp == head), queried = Z * Q_pos @ KV.
// ---------------------------------------------------------------------------
__global__ void __launch_bounds__(256) stageC_kernel(
    const float* __restrict__ query, const float* __restrict__ xpe,
    const float* __restrict__ xmask, const float* __restrict__ Ksum,
    const float* __restrict__ KV, float* __restrict__ queried)
{
    const int n = blockIdx.x / CHUNKS;
    const int l0 = (blockIdx.x % CHUNKS) * 128;
    const int c = threadIdx.x;
    const int h = c >> 5, lane = c & 31;

    __shared__ float sKV[KVSZ];   // 32 KB
    __shared__ float sKs[256];
    __shared__ float sQp[256];

    for (int i = c; i < KVSZ; i += 256) sKV[i] = KV[(size_t)n*KVSZ + i];
    sKs[c] = Ksum[n*CC + c];
    __syncthreads();

    const size_t base = ((size_t)n * LQ + l0) * CC;
    for (int r = 0; r < 128; r++) {
        size_t row = base + (size_t)r * CC;
        float q  = query[row + c];
        float qp = query[row + (c ^ 1)];
        float cs = xpe[(row + c) * 2 + 0];
        float sn = xpe[(row + c) * 2 + 1];
        float m  = xmask[(size_t)n * LQ + l0 + r];
        float q2 = (c & 1) ? qp : -qp;
        float Qf   = (q > 0.f ? q + 1.f : expf(q)) * m;
        float Qpos = (q * cs + q2 * sn) * m;

        float p = Qf * sKs[c];
#pragma unroll
        for (int o = 16; o; o >>= 1) p += __shfl_xor_sync(0xffffffffu, p, o);
        float z = 1.f / (p + 1e-6f);

        sQp[c] = Qpos;
        __syncthreads();
        float out = 0.f;
        const float* kvh = &sKV[h*1024];
        const float* qph = &sQp[h*32];
#pragma unroll
        for (int d = 0; d < 32; d++)
            out = fmaf(qph[d], kvh[d*32 + lane], out);
        queried[row + c] = out * z;
        __syncthreads();
    }
}

// ---------------------------------------------------------------------------
// LayerNorm over last dim (256); one warp per row; optional residual add.
// ---------------------------------------------------------------------------
__global__ void __launch_bounds__(256) ln_kernel(
    const float* __restrict__ in, const float* __restrict__ g,
    const float* __restrict__ b, const float* __restrict__ resid,
    float* __restrict__ out)
{
    const int row = blockIdx.x * 8 + (threadIdx.x >> 5);
    const int lane = threadIdx.x & 31;
    const float* p = in + (size_t)row * CC;
    float v[8];
    float s = 0.f;
#pragma unroll
    for (int i = 0; i < 8; i++) { v[i] = p[lane + i*32]; s += v[i]; }
#pragma unroll
    for (int o = 16; o; o >>= 1) s += __shfl_xor_sync(0xffffffffu, s, o);
    float mean = s * (1.f/256.f);
    float s2 = 0.f;
#pragma unroll
    for (int i = 0; i < 8; i++) { float d = v[i] - mean; s2 += d*d; }
#pragma unroll
    for (int o = 16; o; o >>= 1) s2 += __shfl_xor_sync(0xffffffffu, s2, o);
    float rstd = rsqrtf(s2 * (1.f/256.f) + 1e-5f);
#pragma unroll
    for (int i = 0; i < 8; i++) {
        int cch = lane + i*32;
        float o = (v[i] - mean) * rstd * g[cch] + b[cch];
        if (resid) o += resid[(size_t)row * CC + cch];
        out[(size_t)row * CC + cch] = o;
    }
}

// ---------------------------------------------------------------------------
extern "C" void kernel_launch(void* const* d_in, const int* in_sizes, int n_in,
                              void* d_out, int out_size)
{
    const float* x     = (const float*)d_in[0];
    const float* src   = (const float*)d_in[1];
    const float* xpe   = (const float*)d_in[2];
    const float* spe   = (const float*)d_in[3];
    const float* xmask = (const float*)d_in[4];
    const float* smask = (const float*)d_in[5];
    const float* Wq    = (const float*)d_in[6];
    const float* Wk    = (const float*)d_in[7];
    const float* Wv    = (const float*)d_in[8];
    const float* Wm    = (const float*)d_in[9];
    const float* W1    = (const float*)d_in[10];
    const float* W2    = (const float*)d_in[11];
    const float* g1    = (const float*)d_in[12];
    const float* b1    = (const float*)d_in[13];
    const float* g2    = (const float*)d_in[14];
    const float* b2    = (const float*)d_in[15];
    float* out = (float*)d_out;

    float *query, *key, *value, *Kpart, *KVpart, *Ksum, *KV;
    float *queried, *msg, *m1, *hbuf, *h2;
    cudaGetSymbolAddress((void**)&query,   g_query);
    cudaGetSymbolAddress((void**)&key,     g_key);
    cudaGetSymbolAddress((void**)&value,   g_value);
    cudaGetSymbolAddress((void**)&Kpart,   g_Kpart);
    cudaGetSymbolAddress((void**)&KVpart,  g_KVpart);
    cudaGetSymbolAddress((void**)&Ksum,    g_Ksum);
    cudaGetSymbolAddress((void**)&KV,      g_KV);
    cudaGetSymbolAddress((void**)&queried, g_queried);
    cudaGetSymbolAddress((void**)&msg,     g_msg);
    cudaGetSymbolAddress((void**)&m1,      g_m1);
    cudaGetSymbolAddress((void**)&hbuf,    g_h);
    cudaGetSymbolAddress((void**)&h2,      g_h2);

    const int BIG = 1 << 30;  // Ksplit sentinel: never use A2
    dim3 gN256(CC / 128, MTOT / 128);       // (2, 256)
    dim3 gN512(2*CC / 128, MTOT / 128);     // (4, 256)

    // QKV projections
    sgemm_nt<<<gN256, 256>>>(x,   x,   BIG, CC, Wq, query, CC, CC, 0);
    sgemm_nt<<<gN256, 256>>>(src, src, BIG, CC, Wk, key,   CC, CC, 0);
    sgemm_nt<<<gN256, 256>>>(src, src, BIG, CC, Wv, value, CC, CC, 0);

    // Linear-attention KV / Ksum (deterministic two-stage reduction)
    stageB_kernel<<<NB*CHUNKS, 256>>>(key, value, spe, smask, Kpart, KVpart);
    reduce_parts<<<(NB*CC + NB*KVSZ + 255) / 256, 256>>>(Kpart, KVpart, Ksum, KV);

    // Q-side: Z + queried
    stageC_kernel<<<NB*CHUNKS, 256>>>(query, xpe, xmask, Ksum, KV, queried);

    // Message projection + LN1
    sgemm_nt<<<gN256, 256>>>(queried, queried, BIG, CC, Wm, msg, CC, CC, 0);
    ln_kernel<<<MTOT/8, 256>>>(msg, g1, b1, nullptr, m1);

    // MLP: h = relu([x, m1] @ W1^T); h2 = h @ W2^T
    sgemm_nt<<<gN512, 256>>>(x, m1, CC, CC, W1, hbuf, 2*CC, 2*CC, 1);
    sgemm_nt<<<gN256, 256>>>(hbuf, hbuf, BIG, 2*CC, W2, h2, CC, 2*CC, 0);

    // out = x + LN2(h2)
    ln_kernel<<<MTOT/8, 256>>>(h2, g2, b2, x, out);
}

// round 3
// speedup vs baseline: 2.3751x; 2.3751x over previous
#include <cuda_runtime.h>
#include <cuda_bf16.h>
#include <math.h>
#include <stdint.h>

// Problem constants
#define NB 4
#define LQ 8192
#define SSEQ 8192
#define CC 256
#define HH 8
#define DD 32
#define MTOT (NB*LQ)     // 32768 query rows
#define MSRC (NB*SSEQ)   // 32768 source rows
#define CHUNKS 64        // S/128 per batch
#define KVSZ (HH*DD*DD)  // 8192 per batch

// Scratch (device globals: no allocation allowed)
__device__ float g_query[MTOT*CC];
__device__ float g_key[MSRC*CC];
__device__ float g_value[MSRC*CC];
__device__ float g_Kpart[NB*CHUNKS*CC];
__device__ float g_KVpart[(size_t)NB*CHUNKS*KVSZ];
__device__ float g_Ksum[NB*CC];
__device__ float g_KV[NB*KVSZ];
__device__ float g_queried[MTOT*CC];
__device__ float g_msg[MTOT*CC];
__device__ float g_m1[MTOT*CC];
__device__ float g_h[(size_t)MTOT*2*CC];
__device__ float g_h2[MTOT*CC];

// ===========================================================================
// Helpers
// ===========================================================================
__device__ __forceinline__ uint32_t smem_u32(const void* p) {
    uint32_t a;
    asm("{ .reg .u64 t; cvta.to.shared.u64 t, %1; cvt.u32.u64 %0, t; }"
        : "=r"(a) : "l"(p));
    return a;
}
__device__ __forceinline__ uint32_t packbf2(float a, float b) {
    __nv_bfloat162 t = __floats2bfloat162_rn(a, b);
    return reinterpret_cast<uint32_t&>(t);
}
// float4 -> hi (4 bf16) + lo (4 bf16 of residual)
__device__ __forceinline__ void cvt4(float4 v, uint2& hi, uint2& lo) {
    float f[4] = {v.x, v.y, v.z, v.w};
    float hf[4], lf[4];
#pragma unroll
    for (int i = 0; i < 4; i++) {
        __nv_bfloat16 h = __float2bfloat16(f[i]);
        hf[i] = __bfloat162float(h);
        lf[i] = f[i] - hf[i];
    }
    hi = make_uint2(packbf2(hf[0], hf[1]), packbf2(hf[2], hf[3]));
    lo = make_uint2(packbf2(lf[0], lf[1]), packbf2(lf[2], lf[3]));
}

#define LDSM_X4(r0,r1,r2,r3, addr) \
    asm volatile("ldmatrix.sync.aligned.m8n8.x4.shared.b16 {%0,%1,%2,%3}, [%4];" \
        : "=r"(r0), "=r"(r1), "=r"(r2), "=r"(r3) : "r"(addr))
#define LDSM_X2(r0,r1, addr) \
    asm volatile("ldmatrix.sync.aligned.m8n8.x2.shared.b16 {%0,%1}, [%2];" \
        : "=r"(r0), "=r"(r1) : "r"(addr))

__device__ __forceinline__ void mma16816(float* c, const uint32_t* a, const uint32_t* b) {
    asm volatile(
        "mma.sync.aligned.m16n8k16.row.col.f32.bf16.bf16.f32 "
        "{%0,%1,%2,%3}, {%4,%5,%6,%7}, {%8,%9}, {%0,%1,%2,%3};"
        : "+f"(c[0]), "+f"(c[1]), "+f"(c[2]), "+f"(c[3])
        : "r"(a[0]), "r"(a[1]), "r"(a[2]), "r"(a[3]), "r"(b[0]), "r"(b[1]));
}

// ===========================================================================
// Tensor-core GEMM via mma.sync (HMMA fallback path; sm_100 target OK):
//   Y[m,n] = act( sum_k Ain[m,k] * W[n,k] )
// 3-term bf16 split with fp32 accumulation: D += Ah*Bh + Ah*Bl + Al*Bh.
// Tile 128x128xBK32, 8 warps (each 64x32 of m16n8k16 tiles).
// Ain = A for k < Ksplit else A2 (k - Ksplit); both row stride lda.
// W is [Nn, K] row-major. Y is [M, Nn] row-major.
// ===========================================================================
#define BM 128
#define BN 128
#define BK 32
#define SSTR 40   // padded bf16 row stride: 80B -> conflict-free ldmatrix

__global__ void __launch_bounds__(256) hgemm(
    const float* __restrict__ A, const float* __restrict__ A2, int Ksplit, int lda,
    const float* __restrict__ W, float* __restrict__ Y, int Nn, int K, int relu)
{
    __shared__ __align__(16) __nv_bfloat16 Ah[BM*SSTR], Al[BM*SSTR];
    __shared__ __align__(16) __nv_bfloat16 Bh[BN*SSTR], Bl[BN*SSTR];

    const int tid = threadIdx.x;
    const int lane = tid & 31;
    const int wid = tid >> 5;
    const int bm = blockIdx.y * BM;
    const int bn = blockIdx.x * BN;
    const int wm = (wid >> 2) * 64;   // warp m offset (0/64)
    const int wn = (wid & 3) * 32;    // warp n offset (0/32/64/96)

    const uint32_t sAh = smem_u32(Ah), sAl = smem_u32(Al);
    const uint32_t sBh = smem_u32(Bh), sBl = smem_u32(Bl);

    float c[4][4][4];
#pragma unroll
    for (int mi = 0; mi < 4; mi++)
#pragma unroll
        for (int ni = 0; ni < 4; ni++)
#pragma unroll
            for (int i = 0; i < 4; i++) c[mi][ni][i] = 0.f;

    const int lrow = tid >> 3;        // 0..31
    const int lcol = (tid & 7) * 4;   // 0..28

    for (int k0 = 0; k0 < K; k0 += BK) {
        const float* Abase = (k0 < Ksplit)
            ? (A  + (size_t)bm * lda + k0)
            : (A2 + (size_t)bm * lda + (k0 - Ksplit));
#pragma unroll
        for (int r = 0; r < 4; r++) {
            const int row = r * 32 + lrow;
            {
                float4 v = *(const float4*)(Abase + (size_t)row * lda + lcol);
                uint2 hi, lo; cvt4(v, hi, lo);
                *(uint2*)((char*)Ah + (row * SSTR + lcol) * 2) = hi;
                *(uint2*)((char*)Al + (row * SSTR + lcol) * 2) = lo;
            }
            {
                float4 v = *(const float4*)(W + (size_t)(bn + row) * K + k0 + lcol);
                uint2 hi, lo; cvt4(v, hi, lo);
                *(uint2*)((char*)Bh + (row * SSTR + lcol) * 2) = hi;
                *(uint2*)((char*)Bl + (row * SSTR + lcol) * 2) = lo;
            }
        }
        __syncthreads();

#pragma unroll
        for (int kk = 0; kk < 2; kk++) {
            uint32_t ah[4][4], al[4][4], bh[4][2], bl[4][2];
            const uint32_t aoff =
                ((wm + (lane & 15)) * SSTR + kk * 16 + (lane >> 4) * 8) * 2;
#pragma unroll
            for (int mi = 0; mi < 4; mi++) {
                LDSM_X4(ah[mi][0], ah[mi][1], ah[mi][2], ah[mi][3],
                        sAh + aoff + mi * 16 * SSTR * 2);
                LDSM_X4(al[mi][0], al[mi][1], al[mi][2], al[mi][3],
                        sAl + aoff + mi * 16 * SSTR * 2);
            }
            const uint32_t boff =
                ((wn + (lane & 7)) * SSTR + kk * 16 + ((lane >> 3) & 1) * 8) * 2;
#pragma unroll
            for (int ni = 0; ni < 4; ni++) {
                LDSM_X2(bh[ni][0], bh[ni][1], sBh + boff + ni * 8 * SSTR * 2);
                LDSM_X2(bl[ni][0], bl[ni][1], sBl + boff + ni * 8 * SSTR * 2);
            }
#pragma unroll
            for (int mi = 0; mi < 4; mi++)
#pragma unroll
                for (int ni = 0; ni < 4; ni++) {
                    mma16816(c[mi][ni], ah[mi], bh[ni]);
                    mma16816(c[mi][ni], ah[mi], bl[ni]);
                    mma16816(c[mi][ni], al[mi], bh[ni]);
                }
        }
        __syncthreads();
    }

    // Epilogue: c frag mapping (m16n8): rows lane/4 (+8), cols (lane%4)*2 (+1)
    const int grp = lane >> 2;
    const int tg = (lane & 3) * 2;
#pragma unroll
    for (int mi = 0; mi < 4; mi++)
#pragma unroll
        for (int ni = 0; ni < 4; ni++) {
            float v0 = c[mi][ni][0], v1 = c[mi][ni][1];
            float v2 = c[mi][ni][2], v3 = c[mi][ni][3];
            if (relu) {
                v0 = fmaxf(v0, 0.f); v1 = fmaxf(v1, 0.f);
                v2 = fmaxf(v2, 0.f); v3 = fmaxf(v3, 0.f);
            }
            const size_t r0 = (size_t)(bm + wm + mi * 16 + grp) * Nn + bn + wn + ni * 8 + tg;
            const size_t r1 = r0 + (size_t)8 * Nn;
            *(float2*)(Y + r0) = make_float2(v0, v1);
            *(float2*)(Y + r1) = make_float2(v2, v3);
        }
}

// ---------------------------------------------------------------------------
// Stage B: per source row — K = (elu(key)+1)*mask, K_pos = rotary(key)*mask,
// V = rotary(value)*mask. Per-chunk deterministic partials of Ksum and KV.
// ---------------------------------------------------------------------------
__global__ void __launch_bounds__(256) stageB_kernel(
    const float* __restrict__ key, const float* __restrict__ value,
    const float* __restrict__ spe, const float* __restrict__ smask,
    float* __restrict__ Kpart, float* __restrict__ KVpart)
{
    const int n = blockIdx.x / CHUNKS;
    const int chunk = blockIdx.x % CHUNKS;
    const int s0 = chunk * 128;
    const int c = threadIdx.x;
    const int h = c >> 5, lane = c & 31;
    const int d_base = (lane & 7) * 4;
    const int v_base = (lane >> 3) * 8;

    __shared__ float sKp[256], sV[256];
    float accKV[4][8];
#pragma unroll
    for (int i = 0; i < 4; i++)
#pragma unroll
        for (int j = 0; j < 8; j++) accKV[i][j] = 0.f;
    float accKs = 0.f;

    const size_t base = ((size_t)n * SSEQ + s0) * CC;
    for (int r = 0; r < 128; r++) {
        size_t row = base + (size_t)r * CC;
        float kc = key[row + c];
        float kp = key[row + (c ^ 1)];
        float vc = value[row + c];
        float vp = value[row + (c ^ 1)];
        float cs = spe[(row + c) * 2 + 0];
        float sn = spe[(row + c) * 2 + 1];
        float m  = smask[(size_t)n * SSEQ + s0 + r];
        float k2 = (c & 1) ? kp : -kp;
        float v2 = (c & 1) ? vp : -vp;
        float Kf   = (kc > 0.f ? kc + 1.f : expf(kc)) * m;
        float Kpos = (kc * cs + k2 * sn) * m;
        float Vr   = (vc * cs + v2 * sn) * m;
        accKs += Kf;
        sKp[c] = Kpos; sV[c] = Vr;
        __syncthreads();
        float a[4], b[8];
#pragma unroll
        for (int i = 0; i < 4; i++) a[i] = sKp[h*32 + d_base + i];
#pragma unroll
        for (int j = 0; j < 8; j++) b[j] = sV[h*32 + v_base + j];
#pragma unroll
        for (int i = 0; i < 4; i++)
#pragma unroll
            for (int j = 0; j < 8; j++)
                accKV[i][j] = fmaf(a[i], b[j], accKV[i][j]);
        __syncthreads();
    }
    Kpart[(size_t)(n*CHUNKS + chunk)*CC + c] = accKs;
    size_t kvb = (size_t)(n*CHUNKS + chunk)*KVSZ + h*1024;
#pragma unroll
    for (int i = 0; i < 4; i++)
#pragma unroll
        for (int j = 0; j < 8; j++)
            KVpart[kvb + (d_base+i)*32 + v_base + j] = accKV[i][j];
}

// Fixed-order reduction of chunk partials -> Ksum, KV (deterministic)
__global__ void __launch_bounds__(256) reduce_parts(
    const float* __restrict__ Kpart, const float* __restrict__ KVpart,
    float* __restrict__ Ksum, float* __restrict__ KV)
{
    int idx = blockIdx.x * 256 + threadIdx.x;
    if (idx < NB*CC) {
        int n = idx / CC, c = idx % CC;
        float s = 0.f;
        for (int ch = 0; ch < CHUNKS; ch++)
            s += Kpart[(size_t)(n*CHUNKS + ch)*CC + c];
        Ksum[idx] = s;
        return;
    }
    int kidx = idx - NB*CC;
    if (kidx < NB*KVSZ) {
        int n = kidx / KVSZ, e = kidx % KVSZ;
        float s = 0.f;
        for (int ch = 0; ch < CHUNKS; ch++)
            s += KVpart[(size_t)(n*CHUNKS + ch)*KVSZ + e];
        KV[kidx] = s;
    }
}

// ---------------------------------------------------------------------------
// Stage C: Q = (elu(query)+1)*mask, Q_pos = rotary(query)*mask,
// Z = 1/(Q·Ksum + eps) per head, queried = Z * Q_pos @ KV.
// ---------------------------------------------------------------------------
__global__ void __launch_bounds__(256) stageC_kernel(
    const float* __restrict__ query, const float* __restrict__ xpe,
    const float* __restrict__ xmask, const float* __restrict__ Ksum,
    const float* __restrict__ KV, float* __restrict__ queried)
{
    const int n = blockIdx.x / CHUNKS;
    const int l0 = (blockIdx.x % CHUNKS) * 128;
    const int c = threadIdx.x;
    const int h = c >> 5, lane = c & 31;

    __shared__ float sKV[KVSZ];
    __shared__ float sKs[256];
    __shared__ float sQp[256];

    for (int i = c; i < KVSZ; i += 256) sKV[i] = KV[(size_t)n*KVSZ + i];
    sKs[c] = Ksum[n*CC + c];
    __syncthreads();

    const size_t base = ((size_t)n * LQ + l0) * CC;
    for (int r = 0; r < 128; r++) {
        size_t row = base + (size_t)r * CC;
        float q  = query[row + c];
        float qp = query[row + (c ^ 1)];
        float cs = xpe[(row + c) * 2 + 0];
        float sn = xpe[(row + c) * 2 + 1];
        float m  = xmask[(size_t)n * LQ + l0 + r];
        float q2 = (c & 1) ? qp : -qp;
        float Qf   = (q > 0.f ? q + 1.f : expf(q)) * m;
        float Qpos = (q * cs + q2 * sn) * m;

        float p = Qf * sKs[c];
#pragma unroll
        for (int o = 16; o; o >>= 1) p += __shfl_xor_sync(0xffffffffu, p, o);
        float z = 1.f / (p + 1e-6f);

        sQp[c] = Qpos;
        __syncthreads();
        float out = 0.f;
        const float* kvh = &sKV[h*1024];
        const float* qph = &sQp[h*32];
#pragma unroll
        for (int d = 0; d < 32; d++)
            out = fmaf(qph[d], kvh[d*32 + lane], out);
        queried[row + c] = out * z;
        __syncthreads();
    }
}

// ---------------------------------------------------------------------------
// LayerNorm over last dim (256); one warp per row; optional residual add.
// ---------------------------------------------------------------------------
__global__ void __launch_bounds__(256) ln_kernel(
    const float* __restrict__ in, const float* __restrict__ g,
    const float* __restrict__ b, const float* __restrict__ resid,
    float* __restrict__ out)
{
    const int row = blockIdx.x * 8 + (threadIdx.x >> 5);
    const int lane = threadIdx.x & 31;
    const float* p = in + (size_t)row * CC;
    float v[8];
    float s = 0.f;
#pragma unroll
    for (int i = 0; i < 8; i++) { v[i] = p[lane + i*32]; s += v[i]; }
#pragma unroll
    for (int o = 16; o; o >>= 1) s += __shfl_xor_sync(0xffffffffu, s, o);
    float mean = s * (1.f/256.f);
    float s2 = 0.f;
#pragma unroll
    for (int i = 0; i < 8; i++) { float d = v[i] - mean; s2 += d*d; }
#pragma unroll
    for (int o = 16; o; o >>= 1) s2 += __shfl_xor_sync(0xffffffffu, s2, o);
    float rstd = rsqrtf(s2 * (1.f/256.f) + 1e-5f);
#pragma unroll
    for (int i = 0; i < 8; i++) {
        int cch = lane + i*32;
        float o = (v[i] - mean) * rstd * g[cch] + b[cch];
        if (resid) o += resid[(size_t)row * CC + cch];
        out[(size_t)row * CC + cch] = o;
    }
}

// ---------------------------------------------------------------------------
extern "C" void kernel_launch(void* const* d_in, const int* in_sizes, int n_in,
                              void* d_out, int out_size)
{
    const float* x     = (const float*)d_in[0];
    const float* src   = (const float*)d_in[1];
    const float* xpe   = (const float*)d_in[2];
    const float* spe   = (const float*)d_in[3];
    const float* xmask = (const float*)d_in[4];
    const float* smask = (const float*)d_in[5];
    const float* Wq    = (const float*)d_in[6];
    const float* Wk    = (const float*)d_in[7];
    const float* Wv    = (const float*)d_in[8];
    const float* Wm    = (const float*)d_in[9];
    const float* W1    = (const float*)d_in[10];
    const float* W2    = (const float*)d_in[11];
    const float* g1    = (const float*)d_in[12];
    const float* b1    = (const float*)d_in[13];
    const float* g2    = (const float*)d_in[14];
    const float* b2    = (const float*)d_in[15];
    float* out = (float*)d_out;

    float *query, *key, *value, *Kpart, *KVpart, *Ksum, *KV;
    float *queried, *msg, *m1, *hbuf, *h2;
    cudaGetSymbolAddress((void**)&query,   g_query);
    cudaGetSymbolAddress((void**)&key,     g_key);
    cudaGetSymbolAddress((void**)&value,   g_value);
    cudaGetSymbolAddress((void**)&Kpart,   g_Kpart);
    cudaGetSymbolAddress((void**)&KVpart,  g_KVpart);
    cudaGetSymbolAddress((void**)&Ksum,    g_Ksum);
    cudaGetSymbolAddress((void**)&KV,      g_KV);
    cudaGetSymbolAddress((void**)&queried, g_queried);
    cudaGetSymbolAddress((void**)&msg,     g_msg);
    cudaGetSymbolAddress((void**)&m1,      g_m1);
    cudaGetSymbolAddress((void**)&hbuf,    g_h);
    cudaGetSymbolAddress((void**)&h2,      g_h2);

    const int BIG = 1 << 30;  // Ksplit sentinel: never use A2
    dim3 gN256(CC / 128, MTOT / 128);       // (2, 256)
    dim3 gN512(2*CC / 128, MTOT / 128);     // (4, 256)

    // QKV projections (tensor cores via mma.sync, split-bf16)
    hgemm<<<gN256, 256>>>(x,   x,   BIG, CC, Wq, query, CC, CC, 0);
    hgemm<<<gN256, 256>>>(src, src, BIG, CC, Wk, key,   CC, CC, 0);
    hgemm<<<gN256, 256>>>(src, src, BIG, CC, Wv, value, CC, CC, 0);

    // Linear-attention KV / Ksum (deterministic two-stage reduction)
    stageB_kernel<<<NB*CHUNKS, 256>>>(key, value, spe, smask, Kpart, KVpart);
    reduce_parts<<<(NB*CC + NB*KVSZ + 255) / 256, 256>>>(Kpart, KVpart, Ksum, KV);

    // Q-side: Z + queried
    stageC_kernel<<<NB*CHUNKS, 256>>>(query, xpe, xmask, Ksum, KV, queried);

    // Message projection + LN1
    hgemm<<<gN256, 256>>>(queried, queried, BIG, CC, Wm, msg, CC, CC, 0);
    ln_kernel<<<MTOT/8, 256>>>(msg, g1, b1, nullptr, m1);

    // MLP: h = relu([x, m1] @ W1^T); h2 = h @ W2^T
    hgemm<<<gN512, 256>>>(x, m1, CC, CC, W1, hbuf, 2*CC, 2*CC, 1);
    hgemm<<<gN256, 256>>>(hbuf, hbuf, BIG, 2*CC, W2, h2, CC, 2*CC, 0);

    // out = x + LN2(h2)
    ln_kernel<<<MTOT/8, 256>>>(h2, g2, b2, x, out);
}

// round 4
// speedup vs baseline: 2.4592x; 1.0354x over previous
#include <cuda_runtime.h>
#include <cuda_bf16.h>
#include <math.h>
#include <stdint.h>

// Problem constants
#define NB 4
#define LQ 8192
#define SSEQ 8192
#define CC 256
#define HH 8
#define DD 32
#define MTOT (NB*LQ)     // 32768 query rows
#define MSRC (NB*SSEQ)   // 32768 source rows
#define CHUNKS 64        // S/128 per batch
#define KVSZ (HH*DD*DD)  // 8192 per batch

// Scratch (device globals: no allocation allowed)
__device__ float g_query[MTOT*CC];
__device__ float g_key[MSRC*CC];
__device__ float g_value[MSRC*CC];
__device__ float g_Kpart[NB*CHUNKS*CC];
__device__ float g_KVpart[(size_t)NB*CHUNKS*KVSZ];
__device__ float g_Ksum[NB*CC];
__device__ float g_KV[NB*KVSZ];
__device__ float g_queried[MTOT*CC];
__device__ float g_msg[MTOT*CC];
__device__ float g_m1[MTOT*CC];
__device__ float g_h[(size_t)MTOT*2*CC];
__device__ float g_h2[MTOT*CC];

// ===========================================================================
// Helpers
// ===========================================================================
__device__ __forceinline__ uint32_t smem_u32(const void* p) {
    uint32_t a;
    asm("{ .reg .u64 t; cvta.to.shared.u64 t, %1; cvt.u32.u64 %0, t; }"
        : "=r"(a) : "l"(p));
    return a;
}
__device__ __forceinline__ uint32_t packbf2(float a, float b) {
    __nv_bfloat162 t = __floats2bfloat162_rn(a, b);
    return reinterpret_cast<uint32_t&>(t);
}
// float4 -> hi (4 bf16) + lo (4 bf16 of residual)
__device__ __forceinline__ void cvt4(float4 v, uint2& hi, uint2& lo) {
    float f[4] = {v.x, v.y, v.z, v.w};
    float hf[4], lf[4];
#pragma unroll
    for (int i = 0; i < 4; i++) {
        __nv_bfloat16 h = __float2bfloat16(f[i]);
        hf[i] = __bfloat162float(h);
        lf[i] = f[i] - hf[i];
    }
    hi = make_uint2(packbf2(hf[0], hf[1]), packbf2(hf[2], hf[3]));
    lo = make_uint2(packbf2(lf[0], lf[1]), packbf2(lf[2], lf[3]));
}

#define LDSM_X4(r0,r1,r2,r3, addr) \
    asm volatile("ldmatrix.sync.aligned.m8n8.x4.shared.b16 {%0,%1,%2,%3}, [%4];" \
        : "=r"(r0), "=r"(r1), "=r"(r2), "=r"(r3) : "r"(addr))
#define LDSM_X2(r0,r1, addr) \
    asm volatile("ldmatrix.sync.aligned.m8n8.x2.shared.b16 {%0,%1}, [%2];" \
        : "=r"(r0), "=r"(r1) : "r"(addr))

__device__ __forceinline__ void mma16816(float* c, const uint32_t* a, const uint32_t* b) {
    asm volatile(
        "mma.sync.aligned.m16n8k16.row.col.f32.bf16.bf16.f32 "
        "{%0,%1,%2,%3}, {%4,%5,%6,%7}, {%8,%9}, {%0,%1,%2,%3};"
        : "+f"(c[0]), "+f"(c[1]), "+f"(c[2]), "+f"(c[3])
        : "r"(a[0]), "r"(a[1]), "r"(a[2]), "r"(a[3]), "r"(b[0]), "r"(b[1]));
}

// ===========================================================================
// Tensor-core GEMM via mma.sync, software-pipelined:
//   Y[m,n] = act( sum_k Ain[m,k] * W[n,k] )
// 3-term bf16 split, fp32 accum: D += Ah*Bh + Ah*Bl + Al*Bh.
// Tile 128x128xBK32, 512 threads / 16 warps (warp tile 32x32).
// Double-buffered smem; GMEM prefetch to regs overlaps MMA.
// ===========================================================================
#define BM 128
#define BN 128
#define BK 32
#define SSTR 40                 // padded bf16 row stride (80B): conflict-free ldmatrix
#define TILEB (128*SSTR*2)      // bytes per array (10240)
#define BUFB (4*TILEB)          // bytes per buffer (Ah,Al,Bh,Bl)
#define SMEM_DYN (2*BUFB)       // 81920

__global__ void __launch_bounds__(512) hgemm(
    const float* __restrict__ A, const float* __restrict__ A2, int Ksplit, int lda,
    const float* __restrict__ W, float* __restrict__ Y, int Nn, int K, int relu)
{
    extern __shared__ __align__(16) char smem[];
    const uint32_t sb = smem_u32(smem);

    const int tid = threadIdx.x;
    const int lane = tid & 31;
    const int wid = tid >> 5;
    const int bm = blockIdx.y * BM;
    const int bn = blockIdx.x * BN;
    const int wm = (wid >> 2) * 32;   // warp m offset (0..96)
    const int wn = (wid & 3) * 32;    // warp n offset (0..96)

    float c[2][4][4];
#pragma unroll
    for (int mi = 0; mi < 2; mi++)
#pragma unroll
        for (int ni = 0; ni < 4; ni++)
#pragma unroll
            for (int i = 0; i < 4; i++) c[mi][ni][i] = 0.f;

    const int lrow = tid >> 3;        // 0..63
    const int lcol = (tid & 7) * 4;   // 0..28

    const int nk = K / BK;
    float4 pa[2], pb[2];

    // prefetch chunk 0
    {
        const float* Abase = (0 < Ksplit) ? (A + (size_t)bm * lda)
                                          : (A2 + (size_t)bm * lda - Ksplit);
#pragma unroll
        for (int r = 0; r < 2; r++) {
            const int row = r * 64 + lrow;
            pa[r] = *(const float4*)(Abase + (size_t)row * lda + lcol);
            pb[r] = *(const float4*)(W + (size_t)(bn + row) * K + lcol);
        }
    }

    int buf = 0;
    for (int ck = 0; ck < nk; ck++) {
        // convert + store prefetched chunk into smem[buf]
        char* pbuf = smem + buf * BUFB;
#pragma unroll
        for (int r = 0; r < 2; r++) {
            const int row = r * 64 + lrow;
            const int off = (row * SSTR + lcol) * 2;
            uint2 hi, lo;
            cvt4(pa[r], hi, lo);
            *(uint2*)(pbuf + off)          = hi;
            *(uint2*)(pbuf + TILEB + off)  = lo;
            cvt4(pb[r], hi, lo);
            *(uint2*)(pbuf + 2*TILEB + off) = hi;
            *(uint2*)(pbuf + 3*TILEB + off) = lo;
        }
        __syncthreads();

        // prefetch next chunk (overlaps with MMA below)
        if (ck + 1 < nk) {
            const int k0 = (ck + 1) * BK;
            const float* Abase = (k0 < Ksplit)
                ? (A  + (size_t)bm * lda + k0)
                : (A2 + (size_t)bm * lda + (k0 - Ksplit));
#pragma unroll
            for (int r = 0; r < 2; r++) {
                const int row = r * 64 + lrow;
                pa[r] = *(const float4*)(Abase + (size_t)row * lda + lcol);
                pb[r] = *(const float4*)(W + (size_t)(bn + row) * K + k0 + lcol);
            }
        }

        // MMA on smem[buf]
        const uint32_t sAh = sb + buf * BUFB;
        const uint32_t sAl = sAh + TILEB;
        const uint32_t sBh = sAh + 2*TILEB;
        const uint32_t sBl = sAh + 3*TILEB;
#pragma unroll
        for (int kk = 0; kk < 2; kk++) {
            uint32_t ah[2][4], al[2][4], bh[4][2], bl[4][2];
            const uint32_t aoff =
                ((wm + (lane & 15)) * SSTR + kk * 16 + (lane >> 4) * 8) * 2;
#pragma unroll
            for (int mi = 0; mi < 2; mi++) {
                LDSM_X4(ah[mi][0], ah[mi][1], ah[mi][2], ah[mi][3],
                        sAh + aoff + mi * 16 * SSTR * 2);
                LDSM_X4(al[mi][0], al[mi][1], al[mi][2], al[mi][3],
                        sAl + aoff + mi * 16 * SSTR * 2);
            }
            const uint32_t boff =
                ((wn + (lane & 7)) * SSTR + kk * 16 + ((lane >> 3) & 1) * 8) * 2;
#pragma unroll
            for (int ni = 0; ni < 4; ni++) {
                LDSM_X2(bh[ni][0], bh[ni][1], sBh + boff + ni * 8 * SSTR * 2);
                LDSM_X2(bl[ni][0], bl[ni][1], sBl + boff + ni * 8 * SSTR * 2);
            }
#pragma unroll
            for (int mi = 0; mi < 2; mi++)
#pragma unroll
                for (int ni = 0; ni < 4; ni++) {
                    mma16816(c[mi][ni], ah[mi], bh[ni]);
                    mma16816(c[mi][ni], ah[mi], bl[ni]);
                    mma16816(c[mi][ni], al[mi], bh[ni]);
                }
        }
        buf ^= 1;
    }

    // Epilogue: c frag mapping (m16n8): rows lane/4 (+8), cols (lane%4)*2 (+1)
    const int grp = lane >> 2;
    const int tg = (lane & 3) * 2;
#pragma unroll
    for (int mi = 0; mi < 2; mi++)
#pragma unroll
        for (int ni = 0; ni < 4; ni++) {
            float v0 = c[mi][ni][0], v1 = c[mi][ni][1];
            float v2 = c[mi][ni][2], v3 = c[mi][ni][3];
            if (relu) {
                v0 = fmaxf(v0, 0.f); v1 = fmaxf(v1, 0.f);
                v2 = fmaxf(v2, 0.f); v3 = fmaxf(v3, 0.f);
            }
            const size_t r0 = (size_t)(bm + wm + mi * 16 + grp) * Nn + bn + wn + ni * 8 + tg;
            const size_t r1 = r0 + (size_t)8 * Nn;
            *(float2*)(Y + r0) = make_float2(v0, v1);
            *(float2*)(Y + r1) = make_float2(v2, v3);
        }
}

// ---------------------------------------------------------------------------
// Stage B (warp-per-head, no block syncs): K = (elu(key)+1)*mask,
// K_pos = rotary(key)*mask, V = rotary(value)*mask.
// Per-chunk deterministic partials of Ksum and KV, accumulated in registers.
// ---------------------------------------------------------------------------
__global__ void __launch_bounds__(256) stageB_kernel(
    const float* __restrict__ key, const float* __restrict__ value,
    const float* __restrict__ spe, const float* __restrict__ smask,
    float* __restrict__ Kpart, float* __restrict__ KVpart)
{
    const int n = blockIdx.x / CHUNKS;
    const int chunk = blockIdx.x % CHUNKS;
    const int s0 = chunk * 128;
    const int h = threadIdx.x >> 5;       // warp == head
    const int lane = threadIdx.x & 31;
    const int c = h * 32 + lane;

    float acc[32];
#pragma unroll
    for (int d = 0; d < 32; d++) acc[d] = 0.f;
    float accKs = 0.f;

    const size_t base = ((size_t)n * SSEQ + s0) * CC;
    const float* mrow = smask + (size_t)n * SSEQ + s0;
    for (int r = 0; r < 128; r++) {
        const size_t row = base + (size_t)r * CC;
        float kc = key[row + c];
        float vc = value[row + c];
        float2 pe = *(const float2*)(spe + (row + c) * 2);
        float m  = mrow[r];
        float kp = __shfl_xor_sync(0xffffffffu, kc, 1);
        float vp = __shfl_xor_sync(0xffffffffu, vc, 1);
        float k2 = (lane & 1) ? kp : -kp;
        float v2 = (lane & 1) ? vp : -vp;
        float Kf   = (kc > 0.f ? kc + 1.f : expf(kc)) * m;
        float Kpos = (kc * pe.x + k2 * pe.y) * m;
        float Vr   = (vc * pe.x + v2 * pe.y) * m;
        accKs += Kf;
#pragma unroll
        for (int d = 0; d < 32; d++) {
            float a = __shfl_sync(0xffffffffu, Kpos, d);
            acc[d] = fmaf(a, Vr, acc[d]);
        }
    }
    Kpart[(size_t)(n*CHUNKS + chunk)*CC + c] = accKs;
    const size_t kvb = (size_t)(n*CHUNKS + chunk)*KVSZ + h*1024;
#pragma unroll
    for (int d = 0; d < 32; d++)
        KVpart[kvb + d*32 + lane] = acc[d];
}

// Fixed-order reduction of chunk partials -> Ksum, KV (deterministic)
__global__ void __launch_bounds__(256) reduce_parts(
    const float* __restrict__ Kpart, const float* __restrict__ KVpart,
    float* __restrict__ Ksum, float* __restrict__ KV)
{
    int idx = blockIdx.x * 256 + threadIdx.x;
    if (idx < NB*CC) {
        int n = idx / CC, c = idx % CC;
        float s = 0.f;
        for (int ch = 0; ch < CHUNKS; ch++)
            s += Kpart[(size_t)(n*CHUNKS + ch)*CC + c];
        Ksum[idx] = s;
        return;
    }
    int kidx = idx - NB*CC;
    if (kidx < NB*KVSZ) {
        int n = kidx / KVSZ, e = kidx % KVSZ;
        float s = 0.f;
        for (int ch = 0; ch < CHUNKS; ch++)
            s += KVpart[(size_t)(n*CHUNKS + ch)*KVSZ + e];
        KV[kidx] = s;
    }
}

// ---------------------------------------------------------------------------
// Stage C (warp-per-head): Q = (elu(query)+1)*mask, Q_pos = rotary(query)*mask,
// Z = 1/(Q·Ksum + eps), queried = Z * Q_pos @ KV. KV register-resident.
// ---------------------------------------------------------------------------
__global__ void __launch_bounds__(256) stageC_kernel(
    const float* __restrict__ query, const float* __restrict__ xpe,
    const float* __restrict__ xmask, const float* __restrict__ Ksum,
    const float* __restrict__ KV, float* __restrict__ queried)
{
    const int n = blockIdx.x / CHUNKS;
    const int l0 = (blockIdx.x % CHUNKS) * 128;
    const int h = threadIdx.x >> 5;
    const int lane = threadIdx.x & 31;
    const int c = h * 32 + lane;

    float kvreg[32];   // kvreg[d] = KV[h][d][v=lane]
#pragma unroll
    for (int d = 0; d < 32; d++)
        kvreg[d] = KV[(size_t)n*KVSZ + h*1024 + d*32 + lane];
    const float ks = Ksum[n*CC + c];

    const size_t base = ((size_t)n * LQ + l0) * CC;
    const float* mrow = xmask + (size_t)n * LQ + l0;
    for (int r = 0; r < 128; r++) {
        const size_t row = base + (size_t)r * CC;
        float q  = query[row + c];
        float2 pe = *(const float2*)(xpe + (row + c) * 2);
        float m  = mrow[r];
        float qp = __shfl_xor_sync(0xffffffffu, q, 1);
        float q2 = (lane & 1) ? qp : -qp;
        float Qf   = (q > 0.f ? q + 1.f : expf(q)) * m;
        float Qpos = (q * pe.x + q2 * pe.y) * m;

        float p = Qf * ks;
#pragma unroll
        for (int o = 16; o; o >>= 1) p += __shfl_xor_sync(0xffffffffu, p, o);
        float z = 1.f / (p + 1e-6f);

        float out = 0.f;
#pragma unroll
        for (int d = 0; d < 32; d++) {
            float a = __shfl_sync(0xffffffffu, Qpos, d);
            out = fmaf(a, kvreg[d], out);
        }
        queried[row + c] = out * z;
    }
}

// ---------------------------------------------------------------------------
// LayerNorm over last dim (256); one warp per row; optional residual add.
// ---------------------------------------------------------------------------
__global__ void __launch_bounds__(256) ln_kernel(
    const float* __restrict__ in, const float* __restrict__ g,
    const float* __restrict__ b, const float* __restrict__ resid,
    float* __restrict__ out)
{
    const int row = blockIdx.x * 8 + (threadIdx.x >> 5);
    const int lane = threadIdx.x & 31;
    const float* p = in + (size_t)row * CC;
    float v[8];
    float s = 0.f;
#pragma unroll
    for (int i = 0; i < 8; i++) { v[i] = p[lane + i*32]; s += v[i]; }
#pragma unroll
    for (int o = 16; o; o >>= 1) s += __shfl_xor_sync(0xffffffffu, s, o);
    float mean = s * (1.f/256.f);
    float s2 = 0.f;
#pragma unroll
    for (int i = 0; i < 8; i++) { float d = v[i] - mean; s2 += d*d; }
#pragma unroll
    for (int o = 16; o; o >>= 1) s2 += __shfl_xor_sync(0xffffffffu, s2, o);
    float rstd = rsqrtf(s2 * (1.f/256.f) + 1e-5f);
#pragma unroll
    for (int i = 0; i < 8; i++) {
        int cch = lane + i*32;
        float o = (v[i] - mean) * rstd * g[cch] + b[cch];
        if (resid) o += resid[(size_t)row * CC + cch];
        out[(size_t)row * CC + cch] = o;
    }
}

// ---------------------------------------------------------------------------
extern "C" void kernel_launch(void* const* d_in, const int* in_sizes, int n_in,
                              void* d_out, int out_size)
{
    const float* x     = (const float*)d_in[0];
    const float* src   = (const float*)d_in[1];
    const float* xpe   = (const float*)d_in[2];
    const float* spe   = (const float*)d_in[3];
    const float* xmask = (const float*)d_in[4];
    const float* smask = (const float*)d_in[5];
    const float* Wq    = (const float*)d_in[6];
    const float* Wk    = (const float*)d_in[7];
    const float* Wv    = (const float*)d_in[8];
    const float* Wm    = (const float*)d_in[9];
    const float* W1    = (const float*)d_in[10];
    const float* W2    = (const float*)d_in[11];
    const float* g1    = (const float*)d_in[12];
    const float* b1    = (const float*)d_in[13];
    const float* g2    = (const float*)d_in[14];
    const float* b2    = (const float*)d_in[15];
    float* out = (float*)d_out;

    float *query, *key, *value, *Kpart, *KVpart, *Ksum, *KV;
    float *queried, *msg, *m1, *hbuf, *h2;
    cudaGetSymbolAddress((void**)&query,   g_query);
    cudaGetSymbolAddress((void**)&key,     g_key);
    cudaGetSymbolAddress((void**)&value,   g_value);
    cudaGetSymbolAddress((void**)&Kpart,   g_Kpart);
    cudaGetSymbolAddress((void**)&KVpart,  g_KVpart);
    cudaGetSymbolAddress((void**)&Ksum,    g_Ksum);
    cudaGetSymbolAddress((void**)&KV,      g_KV);
    cudaGetSymbolAddress((void**)&queried, g_queried);
    cudaGetSymbolAddress((void**)&msg,     g_msg);
    cudaGetSymbolAddress((void**)&m1,      g_m1);
    cudaGetSymbolAddress((void**)&hbuf,    g_h);
    cudaGetSymbolAddress((void**)&h2,      g_h2);

    cudaFuncSetAttribute(hgemm, cudaFuncAttributeMaxDynamicSharedMemorySize, SMEM_DYN);

    const int BIG = 1 << 30;  // Ksplit sentinel: never use A2
    dim3 gN256(CC / 128, MTOT / 128);       // (2, 256)
    dim3 gN512(2*CC / 128, MTOT / 128);     // (4, 256)

    // QKV projections (tensor cores via mma.sync, split-bf16, pipelined)
    hgemm<<<gN256, 512, SMEM_DYN>>>(x,   x,   BIG, CC, Wq, query, CC, CC, 0);
    hgemm<<<gN256, 512, SMEM_DYN>>>(src, src, BIG, CC, Wk, key,   CC, CC, 0);
    hgemm<<<gN256, 512, SMEM_DYN>>>(src, src, BIG, CC, Wv, value, CC, CC, 0);

    // Linear-attention KV / Ksum (deterministic two-stage reduction)
    stageB_kernel<<<NB*CHUNKS, 256>>>(key, value, spe, smask, Kpart, KVpart);
    reduce_parts<<<(NB*CC + NB*KVSZ + 255) / 256, 256>>>(Kpart, KVpart, Ksum, KV);

    // Q-side: Z + queried
    stageC_kernel<<<NB*CHUNKS, 256>>>(query, xpe, xmask, Ksum, KV, queried);

    // Message projection + LN1
    hgemm<<<gN256, 512, SMEM_DYN>>>(queried, queried, BIG, CC, Wm, msg, CC, CC, 0);
    ln_kernel<<<MTOT/8, 256>>>(msg, g1, b1, nullptr, m1);

    // MLP: h = relu([x, m1] @ W1^T); h2 = h @ W2^T
    hgemm<<<gN512, 512, SMEM_DYN>>>(x, m1, CC, CC, W1, hbuf, 2*CC, 2*CC, 1);
    hgemm<<<gN256, 512, SMEM_DYN>>>(hbuf, hbuf, BIG, 2*CC, W2, h2, CC, 2*CC, 0);

    // out = x + LN2(h2)
    ln_kernel<<<MTOT/8, 256>>>(h2, g2, b2, x, out);
}

// round 5
// speedup vs baseline: 3.4751x; 1.4131x over previous
#include <cuda_runtime.h>
#include <cuda_fp16.h>
#include <math.h>
#include <stdint.h>

// Problem constants
#define NB 4
#define LQ 8192
#define SSEQ 8192
#define CC 256
#define HH 8
#define DD 32
#define MTOT (NB*LQ)     // 32768 query rows
#define MSRC (NB*SSEQ)   // 32768 source rows
#define SUBC 256         // 32-row chunks per batch
#define KVSZ (HH*DD*DD)  // 8192 per batch

// Scratch (device globals: no allocation allowed)
__device__ float g_query[MTOT*CC];
__device__ float g_key[MSRC*CC];
__device__ float g_value[MSRC*CC];
__device__ float g_Kpart[(size_t)NB*SUBC*CC];
__device__ float g_KVpart[(size_t)NB*SUBC*KVSZ];
__device__ float g_Ksum[NB*CC];
__device__ float g_KV[NB*KVSZ];
__device__ float g_queried[MTOT*CC];
__device__ float g_msg[MTOT*CC];
__device__ float g_m1[MTOT*CC];
__device__ float g_h[(size_t)MTOT*2*CC];
__device__ float g_h2[MTOT*CC];

// ===========================================================================
// Helpers
// ===========================================================================
__device__ __forceinline__ uint32_t smem_u32(const void* p) {
    uint32_t a;
    asm("{ .reg .u64 t; cvta.to.shared.u64 t, %1; cvt.u32.u64 %0, t; }"
        : "=r"(a) : "l"(p));
    return a;
}
__device__ __forceinline__ uint32_t packh2(float a, float b) {
    __half2 t = __floats2half2_rn(a, b);
    return reinterpret_cast<uint32_t&>(t);
}
// float4 -> hi (4 fp16) + lo (4 fp16 residual)
__device__ __forceinline__ void cvt4split(float4 v, uint2& hi, uint2& lo) {
    float f[4] = {v.x, v.y, v.z, v.w};
    float hf[4], lf[4];
#pragma unroll
    for (int i = 0; i < 4; i++) {
        __half h = __float2half_rn(f[i]);
        hf[i] = __half2float(h);
        lf[i] = f[i] - hf[i];
    }
    hi = make_uint2(packh2(hf[0], hf[1]), packh2(hf[2], hf[3]));
    lo = make_uint2(packh2(lf[0], lf[1]), packh2(lf[2], lf[3]));
}
__device__ __forceinline__ uint2 cvt4rnd(float4 v) {
    return make_uint2(packh2(v.x, v.y), packh2(v.z, v.w));
}

#define LDSM_X4(r0,r1,r2,r3, addr) \
    asm volatile("ldmatrix.sync.aligned.m8n8.x4.shared.b16 {%0,%1,%2,%3}, [%4];" \
        : "=r"(r0), "=r"(r1), "=r"(r2), "=r"(r3) : "r"(addr))
#define LDSM_X2(r0,r1, addr) \
    asm volatile("ldmatrix.sync.aligned.m8n8.x2.shared.b16 {%0,%1}, [%2];" \
        : "=r"(r0), "=r"(r1) : "r"(addr))

__device__ __forceinline__ void mma16816(float* c, const uint32_t* a, const uint32_t* b) {
    asm volatile(
        "mma.sync.aligned.m16n8k16.row.col.f32.f16.f16.f32 "
        "{%0,%1,%2,%3}, {%4,%5,%6,%7}, {%8,%9}, {%0,%1,%2,%3};"
        : "+f"(c[0]), "+f"(c[1]), "+f"(c[2]), "+f"(c[3])
        : "r"(a[0]), "r"(a[1]), "r"(a[2]), "r"(a[3]), "r"(b[0]), "r"(b[1]));
}

// ===========================================================================
// Tensor-core GEMM via mma.sync (fp16 2-term split, fp32 accum):
//   Y[m,n] = act( sum_k Ain[m,k] * W[n,k] ),  D = Ah*Bh + Al*Bh
// Tile 64x128xBK32, 256 threads / 8 warps (warp tile 32x32), 2 CTAs/SM.
// Double-buffered smem; GMEM prefetch to regs overlaps MMA.
// ===========================================================================
#define BM 64
#define BN 128
#define BK 32
#define SSTR 40                 // padded fp16 row stride (80B): conflict-free ldmatrix
#define TA (64*SSTR*2)          // 5120 bytes (Ah or Al)
#define TB (128*SSTR*2)         // 10240 bytes (Bh)
#define BUFB (2*TA + TB)        // 20480
#define SMEM_DYN (2*BUFB)       // 40960

__global__ void __launch_bounds__(256, 2) hgemm(
    const float* __restrict__ A, const float* __restrict__ A2, int Ksplit, int lda,
    const float* __restrict__ W, float* __restrict__ Y, int Nn, int K, int relu)
{
    extern __shared__ __align__(16) char smem[];
    const uint32_t sb = smem_u32(smem);

    const int tid = threadIdx.x;
    const int lane = tid & 31;
    const int wid = tid >> 5;
    const int bm = blockIdx.y * BM;
    const int bn = blockIdx.x * BN;
    const int wm = (wid >> 2) * 32;   // 0/32
    const int wn = (wid & 3) * 32;    // 0..96

    float c[2][4][4];
#pragma unroll
    for (int mi = 0; mi < 2; mi++)
#pragma unroll
        for (int ni = 0; ni < 4; ni++)
#pragma unroll
            for (int i = 0; i < 4; i++) c[mi][ni][i] = 0.f;

    const int lrow = tid >> 3;        // 0..31
    const int lcol = (tid & 7) * 4;   // 0..28

    const int nk = K / BK;
    float4 pa[2], pb[4];

    // prefetch chunk 0 (k0=0 is always < Ksplit)
    {
        const float* Abase = A + (size_t)bm * lda;
#pragma unroll
        for (int r = 0; r < 2; r++)
            pa[r] = *(const float4*)(Abase + (size_t)(r*32 + lrow) * lda + lcol);
#pragma unroll
        for (int r = 0; r < 4; r++)
            pb[r] = *(const float4*)(W + (size_t)(bn + r*32 + lrow) * K + lcol);
    }

    int buf = 0;
    for (int ck = 0; ck < nk; ck++) {
        // convert + store prefetched chunk into smem[buf]
        char* pbuf = smem + buf * BUFB;
#pragma unroll
        for (int r = 0; r < 2; r++) {
            const int off = ((r*32 + lrow) * SSTR + lcol) * 2;
            uint2 hi, lo;
            cvt4split(pa[r], hi, lo);
            *(uint2*)(pbuf + off)      = hi;
            *(uint2*)(pbuf + TA + off) = lo;
        }
#pragma unroll
        for (int r = 0; r < 4; r++) {
            const int off = ((r*32 + lrow) * SSTR + lcol) * 2;
            *(uint2*)(pbuf + 2*TA + off) = cvt4rnd(pb[r]);
        }
        __syncthreads();

        // prefetch next chunk (overlaps with MMA below)
        if (ck + 1 < nk) {
            const int k0 = (ck + 1) * BK;
            const float* Abase = (k0 < Ksplit)
                ? (A  + (size_t)bm * lda + k0)
                : (A2 + (size_t)bm * lda + (k0 - Ksplit));
#pragma unroll
            for (int r = 0; r < 2; r++)
                pa[r] = *(const float4*)(Abase + (size_t)(r*32 + lrow) * lda + lcol);
#pragma unroll
            for (int r = 0; r < 4; r++)
                pb[r] = *(const float4*)(W + (size_t)(bn + r*32 + lrow) * K + k0 + lcol);
        }

        // MMA on smem[buf]
        const uint32_t sAh = sb + buf * BUFB;
        const uint32_t sAl = sAh + TA;
        const uint32_t sBh = sAh + 2*TA;
#pragma unroll
        for (int kk = 0; kk < 2; kk++) {
            uint32_t ah[2][4], al[2][4], bh[4][2];
            const uint32_t aoff =
                ((wm + (lane & 15)) * SSTR + kk * 16 + (lane >> 4) * 8) * 2;
#pragma unroll
            for (int mi = 0; mi < 2; mi++) {
                LDSM_X4(ah[mi][0], ah[mi][1], ah[mi][2], ah[mi][3],
                        sAh + aoff + mi * 16 * SSTR * 2);
                LDSM_X4(al[mi][0], al[mi][1], al[mi][2], al[mi][3],
                        sAl + aoff + mi * 16 * SSTR * 2);
            }
            const uint32_t boff =
                ((wn + (lane & 7)) * SSTR + kk * 16 + ((lane >> 3) & 1) * 8) * 2;
#pragma unroll
            for (int ni = 0; ni < 4; ni++)
                LDSM_X2(bh[ni][0], bh[ni][1], sBh + boff + ni * 8 * SSTR * 2);
#pragma unroll
            for (int mi = 0; mi < 2; mi++)
#pragma unroll
                for (int ni = 0; ni < 4; ni++) {
                    mma16816(c[mi][ni], ah[mi], bh[ni]);
                    mma16816(c[mi][ni], al[mi], bh[ni]);
                }
        }
        buf ^= 1;
    }

    // Epilogue: c frag mapping (m16n8): rows lane/4 (+8), cols (lane%4)*2 (+1)
    const int grp = lane >> 2;
    const int tg = (lane & 3) * 2;
#pragma unroll
    for (int mi = 0; mi < 2; mi++)
#pragma unroll
        for (int ni = 0; ni < 4; ni++) {
            float v0 = c[mi][ni][0], v1 = c[mi][ni][1];
            float v2 = c[mi][ni][2], v3 = c[mi][ni][3];
            if (relu) {
                v0 = fmaxf(v0, 0.f); v1 = fmaxf(v1, 0.f);
                v2 = fmaxf(v2, 0.f); v3 = fmaxf(v3, 0.f);
            }
            const size_t r0 = (size_t)(bm + wm + mi * 16 + grp) * Nn + bn + wn + ni * 8 + tg;
            const size_t r1 = r0 + (size_t)8 * Nn;
            *(float2*)(Y + r0) = make_float2(v0, v1);
            *(float2*)(Y + r1) = make_float2(v2, v3);
        }
}

// ---------------------------------------------------------------------------
// Stage B (warp-per-head, 32-row chunks, grid 1024): K = (elu(key)+1)*mask,
// K_pos = rotary(key)*mask, V = rotary(value)*mask. Deterministic partials.
// ---------------------------------------------------------------------------
__global__ void __launch_bounds__(256) stageB_kernel(
    const float* __restrict__ key, const float* __restrict__ value,
    const float* __restrict__ spe, const float* __restrict__ smask,
    float* __restrict__ Kpart, float* __restrict__ KVpart)
{
    const int n = blockIdx.x / SUBC;
    const int chunk = blockIdx.x % SUBC;
    const int s0 = chunk * 32;
    const int h = threadIdx.x >> 5;       // warp == head
    const int lane = threadIdx.x & 31;
    const int c = h * 32 + lane;

    float acc[32];
#pragma unroll
    for (int d = 0; d < 32; d++) acc[d] = 0.f;
    float accKs = 0.f;

    const size_t base = ((size_t)n * SSEQ + s0) * CC;
    const float* mrow = smask + (size_t)n * SSEQ + s0;
    for (int r = 0; r < 32; r++) {
        const size_t row = base + (size_t)r * CC;
        float kc = key[row + c];
        float vc = value[row + c];
        float2 pe = *(const float2*)(spe + (row + c) * 2);
        float m  = mrow[r];
        float kp = __shfl_xor_sync(0xffffffffu, kc, 1);
        float vp = __shfl_xor_sync(0xffffffffu, vc, 1);
        float k2 = (lane & 1) ? kp : -kp;
        float v2 = (lane & 1) ? vp : -vp;
        float Kf   = (kc > 0.f ? kc + 1.f : expf(kc)) * m;
        float Kpos = (kc * pe.x + k2 * pe.y) * m;
        float Vr   = (vc * pe.x + v2 * pe.y) * m;
        accKs += Kf;
#pragma unroll
        for (int d = 0; d < 32; d++) {
            float a = __shfl_sync(0xffffffffu, Kpos, d);
            acc[d] = fmaf(a, Vr, acc[d]);
        }
    }
    Kpart[(size_t)(n*SUBC + chunk)*CC + c] = accKs;
    const size_t kvb = (size_t)(n*SUBC + chunk)*KVSZ + h*1024;
#pragma unroll
    for (int d = 0; d < 32; d++)
        KVpart[kvb + d*32 + lane] = acc[d];
}

// Fixed-order reduction of chunk partials -> Ksum, KV (deterministic)
__global__ void __launch_bounds__(256) reduce_parts(
    const float* __restrict__ Kpart, const float* __restrict__ KVpart,
    float* __restrict__ Ksum, float* __restrict__ KV)
{
    int idx = blockIdx.x * 256 + threadIdx.x;
    if (idx < NB*CC) {
        int n = idx / CC, c = idx % CC;
        float s = 0.f;
        for (int ch = 0; ch < SUBC; ch++)
            s += Kpart[(size_t)(n*SUBC + ch)*CC + c];
        Ksum[idx] = s;
        return;
    }
    int kidx = idx - NB*CC;
    if (kidx < NB*KVSZ) {
        int n = kidx / KVSZ, e = kidx % KVSZ;
        float s = 0.f;
        for (int ch = 0; ch < SUBC; ch++)
            s += KVpart[(size_t)(n*SUBC + ch)*KVSZ + e];
        KV[kidx] = s;
    }
}

// ---------------------------------------------------------------------------
// Stage C (warp-per-head, 32-row blocks, grid 1024): Q = (elu(query)+1)*mask,
// Q_pos = rotary(query)*mask, Z = 1/(Q·Ksum+eps), queried = Z * Q_pos @ KV.
// ---------------------------------------------------------------------------
__global__ void __launch_bounds__(256) stageC_kernel(
    const float* __restrict__ query, const float* __restrict__ xpe,
    const float* __restrict__ xmask, const float* __restrict__ Ksum,
    const float* __restrict__ KV, float* __restrict__ queried)
{
    const int n = blockIdx.x / SUBC;
    const int l0 = (blockIdx.x % SUBC) * 32;
    const int h = threadIdx.x >> 5;
    const int lane = threadIdx.x & 31;
    const int c = h * 32 + lane;

    float kvreg[32];   // kvreg[d] = KV[h][d][v=lane]
#pragma unroll
    for (int d = 0; d < 32; d++)
        kvreg[d] = KV[(size_t)n*KVSZ + h*1024 + d*32 + lane];
    const float ks = Ksum[n*CC + c];

    const size_t base = ((size_t)n * LQ + l0) * CC;
    const float* mrow = xmask + (size_t)n * LQ + l0;
    for (int r = 0; r < 32; r++) {
        const size_t row = base + (size_t)r * CC;
        float q  = query[row + c];
        float2 pe = *(const float2*)(xpe + (row + c) * 2);
        float m  = mrow[r];
        float qp = __shfl_xor_sync(0xffffffffu, q, 1);
        float q2 = (lane & 1) ? qp : -qp;
        float Qf   = (q > 0.f ? q + 1.f : expf(q)) * m;
        float Qpos = (q * pe.x + q2 * pe.y) * m;

        float p = Qf * ks;
#pragma unroll
        for (int o = 16; o; o >>= 1) p += __shfl_xor_sync(0xffffffffu, p, o);
        float z = 1.f / (p + 1e-6f);

        float out = 0.f;
#pragma unroll
        for (int d = 0; d < 32; d++) {
            float a = __shfl_sync(0xffffffffu, Qpos, d);
            out = fmaf(a, kvreg[d], out);
        }
        queried[row + c] = out * z;
    }
}

// ---------------------------------------------------------------------------
// LayerNorm over last dim (256); one warp per row; optional residual add.
// ---------------------------------------------------------------------------
__global__ void __launch_bounds__(256) ln_kernel(
    const float* __restrict__ in, const float* __restrict__ g,
    const float* __restrict__ b, const float* __restrict__ resid,
    float* __restrict__ out)
{
    const int row = blockIdx.x * 8 + (threadIdx.x >> 5);
    const int lane = threadIdx.x & 31;
    const float* p = in + (size_t)row * CC;
    float v[8];
    float s = 0.f;
#pragma unroll
    for (int i = 0; i < 8; i++) { v[i] = p[lane + i*32]; s += v[i]; }
#pragma unroll
    for (int o = 16; o; o >>= 1) s += __shfl_xor_sync(0xffffffffu, s, o);
    float mean = s * (1.f/256.f);
    float s2 = 0.f;
#pragma unroll
    for (int i = 0; i < 8; i++) { float d = v[i] - mean; s2 += d*d; }
#pragma unroll
    for (int o = 16; o; o >>= 1) s2 += __shfl_xor_sync(0xffffffffu, s2, o);
    float rstd = rsqrtf(s2 * (1.f/256.f) + 1e-5f);
#pragma unroll
    for (int i = 0; i < 8; i++) {
        int cch = lane + i*32;
        float o = (v[i] - mean) * rstd * g[cch] + b[cch];
        if (resid) o += resid[(size_t)row * CC + cch];
        out[(size_t)row * CC + cch] = o;
    }
}

// ---------------------------------------------------------------------------
extern "C" void kernel_launch(void* const* d_in, const int* in_sizes, int n_in,
                              void* d_out, int out_size)
{
    const float* x     = (const float*)d_in[0];
    const float* src   = (const float*)d_in[1];
    const float* xpe   = (const float*)d_in[2];
    const float* spe   = (const float*)d_in[3];
    const float* xmask = (const float*)d_in[4];
    const float* smask = (const float*)d_in[5];
    const float* Wq    = (const float*)d_in[6];
    const float* Wk    = (const float*)d_in[7];
    const float* Wv    = (const float*)d_in[8];
    const float* Wm    = (const float*)d_in[9];
    const float* W1    = (const float*)d_in[10];
    const float* W2    = (const float*)d_in[11];
    const float* g1    = (const float*)d_in[12];
    const float* b1    = (const float*)d_in[13];
    const float* g2    = (const float*)d_in[14];
    const float* b2    = (const float*)d_in[15];
    float* out = (float*)d_out;

    float *query, *key, *value, *Kpart, *KVpart, *Ksum, *KV;
    float *queried, *msg, *m1, *hbuf, *h2;
    cudaGetSymbolAddress((void**)&query,   g_query);
    cudaGetSymbolAddress((void**)&key,     g_key);
    cudaGetSymbolAddress((void**)&value,   g_value);
    cudaGetSymbolAddress((void**)&Kpart,   g_Kpart);
    cudaGetSymbolAddress((void**)&KVpart,  g_KVpart);
    cudaGetSymbolAddress((void**)&Ksum,    g_Ksum);
    cudaGetSymbolAddress((void**)&KV,      g_KV);
    cudaGetSymbolAddress((void**)&queried, g_queried);
    cudaGetSymbolAddress((void**)&msg,     g_msg);
    cudaGetSymbolAddress((void**)&m1,      g_m1);
    cudaGetSymbolAddress((void**)&hbuf,    g_h);
    cudaGetSymbolAddress((void**)&h2,      g_h2);

    cudaFuncSetAttribute(hgemm, cudaFuncAttributeMaxDynamicSharedMemorySize, SMEM_DYN);

    const int BIG = 1 << 30;  // Ksplit sentinel: never use A2
    dim3 gN256(CC / BN, MTOT / BM);         // (2, 512)
    dim3 gN512(2*CC / BN, MTOT / BM);       // (4, 512)

    // QKV projections (tensor cores via mma.sync, fp16 2-term split)
    hgemm<<<gN256, 256, SMEM_DYN>>>(x,   x,   BIG, CC, Wq, query, CC, CC, 0);
    hgemm<<<gN256, 256, SMEM_DYN>>>(src, src, BIG, CC, Wk, key,   CC, CC, 0);
    hgemm<<<gN256, 256, SMEM_DYN>>>(src, src, BIG, CC, Wv, value, CC, CC, 0);

    // Linear-attention KV / Ksum (deterministic two-stage reduction)
    stageB_kernel<<<NB*SUBC, 256>>>(key, value, spe, smask, Kpart, KVpart);
    reduce_parts<<<(NB*CC + NB*KVSZ + 255) / 256, 256>>>(Kpart, KVpart, Ksum, KV);

    // Q-side: Z + queried
    stageC_kernel<<<NB*SUBC, 256>>>(query, xpe, xmask, Ksum, KV, queried);

    // Message projection + LN1
    hgemm<<<gN256, 256, SMEM_DYN>>>(queried, queried, BIG, CC, Wm, msg, CC, CC, 0);
    ln_kernel<<<MTOT/8, 256>>>(msg, g1, b1, nullptr, m1);

    // MLP: h = relu([x, m1] @ W1^T); h2 = h @ W2^T
    hgemm<<<gN512, 256, SMEM_DYN>>>(x, m1, CC, CC, W1, hbuf, 2*CC, 2*CC, 1);
    hgemm<<<gN256, 256, SMEM_DYN>>>(hbuf, hbuf, BIG, 2*CC, W2, h2, CC, 2*CC, 0);

    // out = x + LN2(h2)
    ln_kernel<<<MTOT/8, 256>>>(h2, g2, b2, x, out);
}

// round 8
// speedup vs baseline: 3.4989x; 1.0068x over previous
#include <cuda_runtime.h>
#include <cuda_fp16.h>
#include <math.h>
#include <stdint.h>

// Problem constants
#define NB 4
#define LQ 8192
#define SSEQ 8192
#define CC 256
#define HH 8
#define DD 32
#define MTOT (NB*LQ)     // 32768 query rows
#define MSRC (NB*SSEQ)   // 32768 source rows
#define SUBC 256         // 32-row chunks per batch
#define KVSZ (HH*DD*DD)  // 8192 per batch

// fp16 weight arena segment offsets (halves)
#define WH_Q  0
#define WH_K  65536
#define WH_V  131072
#define WH_M  196608
#define WH_1  262144
#define WH_2  524288
#define WH_TOT 655360

// Scratch (device globals: no allocation allowed)
__device__ float g_query[MTOT*CC];
__device__ float g_key[MSRC*CC];
__device__ float g_value[MSRC*CC];
__device__ float g_Kpart[(size_t)NB*SUBC*CC];
__device__ float g_KVpart[(size_t)NB*SUBC*KVSZ];
__device__ float g_Ksum[NB*CC];
__device__ float g_KV[NB*KVSZ];
__device__ float g_msg[MTOT*CC];
__device__ float g_h2[MTOT*CC];
// fp16 hi/lo activation tensors
__device__ __half g_xhi[MTOT*CC],  g_xlo[MTOT*CC];
__device__ __half g_shi[MSRC*CC],  g_slo[MSRC*CC];
__device__ __half g_qhi[MTOT*CC],  g_qlo[MTOT*CC];      // queried
__device__ __half g_m1hi[MTOT*CC], g_m1lo[MTOT*CC];
__device__ __half g_hbhi[(size_t)MTOT*2*CC], g_hblo[(size_t)MTOT*2*CC];
__device__ __half g_wh[WH_TOT];

// ===========================================================================
// Helpers
// ===========================================================================
__device__ __forceinline__ uint32_t smem_u32(const void* p) {
    uint32_t a;
    asm("{ .reg .u64 t; cvta.to.shared.u64 t, %1; cvt.u32.u64 %0, t; }"
        : "=r"(a) : "l"(p));
    return a;
}
__device__ __forceinline__ void split1(float v, __half& hi, __half& lo) {
    hi = __float2half_rn(v);
    lo = __float2half_rn(v - __half2float(hi));
}

#define CP_ASYNC16(dst_u32, src_ptr) \
    asm volatile("cp.async.cg.shared.global [%0], [%1], 16;" \
        :: "r"(dst_u32), "l"(src_ptr))
#define CP_COMMIT() asm volatile("cp.async.commit_group;")
#define CP_WAIT1()  asm volatile("cp.async.wait_group 1;")

#define LDSM_X4(r0,r1,r2,r3, addr) \
    asm volatile("ldmatrix.sync.aligned.m8n8.x4.shared.b16 {%0,%1,%2,%3}, [%4];" \
        : "=r"(r0), "=r"(r1), "=r"(r2), "=r"(r3) : "r"(addr))
#define LDSM_X2(r0,r1, addr) \
    asm volatile("ldmatrix.sync.aligned.m8n8.x2.shared.b16 {%0,%1}, [%2];" \
        : "=r"(r0), "=r"(r1) : "r"(addr))

__device__ __forceinline__ void mma16816(float* c, const uint32_t* a, const uint32_t* b) {
    asm volatile(
        "mma.sync.aligned.m16n8k16.row.col.f32.f16.f16.f32 "
        "{%0,%1,%2,%3}, {%4,%5,%6,%7}, {%8,%9}, {%0,%1,%2,%3};"
        : "+f"(c[0]), "+f"(c[1]), "+f"(c[2]), "+f"(c[3])
        : "r"(a[0]), "r"(a[1]), "r"(a[2]), "r"(a[3]), "r"(b[0]), "r"(b[1]));
}

// ===========================================================================
// One-time converts
// ===========================================================================
__global__ void convert_act(const float* __restrict__ in,
                            __half* __restrict__ hi, __half* __restrict__ lo, int n4)
{
    int i = blockIdx.x * 256 + threadIdx.x;
    if (i >= n4) return;
    float4 v = ((const float4*)in)[i];
    __half h[4], l[4];
    split1(v.x, h[0], l[0]); split1(v.y, h[1], l[1]);
    split1(v.z, h[2], l[2]); split1(v.w, h[3], l[3]);
    ((uint2*)hi)[i] = *(uint2*)h;
    ((uint2*)lo)[i] = *(uint2*)l;
}

__global__ void convert_w(const float* __restrict__ Wq, const float* __restrict__ Wk,
                          const float* __restrict__ Wv, const float* __restrict__ Wm,
                          const float* __restrict__ W1, const float* __restrict__ W2,
                          __half* __restrict__ arena)
{
    int idx = (blockIdx.x * 256 + threadIdx.x) * 4;
    if (idx >= WH_TOT) return;
    const float* src; int off;
    if (idx < WH_1) {
        int seg = idx >> 16;
        src = (seg == 0) ? Wq : (seg == 1) ? Wk : (seg == 2) ? Wv : Wm;
        off = idx & 65535;
    } else if (idx < WH_2) { src = W1; off = idx - WH_1; }
    else                   { src = W2; off = idx - WH_2; }
    float4 v = *(const float4*)(src + off);
    __half h[4] = {__float2half_rn(v.x), __float2half_rn(v.y),
                   __float2half_rn(v.z), __float2half_rn(v.w)};
    *(uint2*)(arena + idx) = *(uint2*)h;
}

// ===========================================================================
// Tensor-core GEMM, cp.async 3-stage pipeline, all-fp16 inputs:
//   Y[m,n] = act( sum_k (Ah+Al)[m,k] * Bh[n,k] )
// Tile 64x128xBK32, 256 threads / 8 warps (warp tile 32x32), 3 CTAs/SM.
// A source = (Ah,Al) with row stride lda for k < Ksplit, else (A2h,A2l)
// (row stride lda) at k-Ksplit. W fp16 [Nn,K] row-major (stride K).
// Out: fp32 Y and/or fp16 hi/lo pair (Yh,Yl).
// ===========================================================================
#define BM 64
#define BN 128
#define BK 32
#define STAGES 3
#define SSTR 40                 // padded fp16 row stride (80B): conflict-free ldmatrix
#define SA (64*SSTR*2)          // 5120 B per A tile (hi or lo)
#define SB (128*SSTR*2)         // 10240 B (Bh)
#define STG (2*SA + SB)         // 20480
#define SMEM_DYN (STAGES*STG)   // 61440

__global__ void __launch_bounds__(256, 3) hgemm(
    const __half* __restrict__ Ah, const __half* __restrict__ Al,
    const __half* __restrict__ A2h, const __half* __restrict__ A2l,
    int Ksplit, int lda, const __half* __restrict__ W,
    float* __restrict__ Y, __half* __restrict__ Yh, __half* __restrict__ Yl,
    int Nn, int K, int relu)
{
    extern __shared__ __align__(16) char smem[];
    const uint32_t sb = smem_u32(smem);

    const int tid = threadIdx.x;
    const int lane = tid & 31;
    const int wid = tid >> 5;
    const int bm = blockIdx.y * BM;
    const int bn = blockIdx.x * BN;
    const int wm = (wid >> 2) * 32;
    const int wn = (wid & 3) * 32;

    // loader mapping: 16B = 8 halves per cp.async
    const int arow = tid >> 2;          // 0..63
    const int acol = (tid & 3) * 8;     // 0,8,16,24
    const uint32_t sAoff = (uint32_t)(arow * SSTR + acol) * 2;

    const int nk = K / BK;

    // issue loads for chunk ck into stage st
    auto load_chunk = [&](int ck, int st) {
        const int k0 = ck * BK;
        const __half* ah; const __half* al;
        int kk0;
        if (k0 < Ksplit) { ah = Ah;  al = Al;  kk0 = k0; }
        else             { ah = A2h; al = A2l; kk0 = k0 - Ksplit; }
        const uint32_t base = sb + st * STG;
        CP_ASYNC16(base + sAoff,      ah + (size_t)(bm + arow) * lda + kk0 + acol);
        CP_ASYNC16(base + SA + sAoff, al + (size_t)(bm + arow) * lda + kk0 + acol);
        CP_ASYNC16(base + 2*SA + sAoff,
                   W + (size_t)(bn + arow) * K + k0 + acol);
        CP_ASYNC16(base + 2*SA + sAoff + (uint32_t)(64 * SSTR * 2),
                   W + (size_t)(bn + 64 + arow) * K + k0 + acol);
    };

    float c[2][4][4];
#pragma unroll
    for (int mi = 0; mi < 2; mi++)
#pragma unroll
        for (int ni = 0; ni < 4; ni++)
#pragma unroll
            for (int i = 0; i < 4; i++) c[mi][ni][i] = 0.f;

    load_chunk(0, 0); CP_COMMIT();
    load_chunk(1, 1); CP_COMMIT();

    for (int ck = 0; ck < nk; ck++) {
        CP_WAIT1();
        __syncthreads();

        const int nc = ck + STAGES - 1;
        if (nc < nk) load_chunk(nc, nc % STAGES);
        CP_COMMIT();

        const uint32_t sAh = sb + (ck % STAGES) * STG;
        const uint32_t sAl = sAh + SA;
        const uint32_t sBh = sAh + 2*SA;
#pragma unroll
        for (int kk = 0; kk < 2; kk++) {
            uint32_t ahf[2][4], alf[2][4], bhf[4][2];
            const uint32_t aoff =
                ((wm + (lane & 15)) * SSTR + kk * 16 + (lane >> 4) * 8) * 2;
#pragma unroll
            for (int mi = 0; mi < 2; mi++) {
                LDSM_X4(ahf[mi][0], ahf[mi][1], ahf[mi][2], ahf[mi][3],
                        sAh + aoff + mi * 16 * SSTR * 2);
                LDSM_X4(alf[mi][0], alf[mi][1], alf[mi][2], alf[mi][3],
                        sAl + aoff + mi * 16 * SSTR * 2);
            }
            const uint32_t boff =
                ((wn + (lane & 7)) * SSTR + kk * 16 + ((lane >> 3) & 1) * 8) * 2;
#pragma unroll
            for (int ni = 0; ni < 4; ni++)
                LDSM_X2(bhf[ni][0], bhf[ni][1], sBh + boff + ni * 8 * SSTR * 2);
#pragma unroll
            for (int mi = 0; mi < 2; mi++)
#pragma unroll
                for (int ni = 0; ni < 4; ni++) {
                    mma16816(c[mi][ni], ahf[mi], bhf[ni]);
                    mma16816(c[mi][ni], alf[mi], bhf[ni]);
                }
        }
        __syncthreads();
    }

    // Epilogue: c frag mapping (m16n8): rows lane/4 (+8), cols (lane%4)*2 (+1)
    const int grp = lane >> 2;
    const int tg = (lane & 3) * 2;
#pragma unroll
    for (int mi = 0; mi < 2; mi++)
#pragma unroll
        for (int ni = 0; ni < 4; ni++) {
            float v[4] = {c[mi][ni][0], c[mi][ni][1], c[mi][ni][2], c[mi][ni][3]};
            if (relu) {
#pragma unroll
                for (int i = 0; i < 4; i++) v[i] = fmaxf(v[i], 0.f);
            }
            const size_t r0 = (size_t)(bm + wm + mi * 16 + grp) * Nn + bn + wn + ni * 8 + tg;
            const size_t r1 = r0 + (size_t)8 * Nn;
            if (Y) {
                *(float2*)(Y + r0) = make_float2(v[0], v[1]);
                *(float2*)(Y + r1) = make_float2(v[2], v[3]);
            }
            if (Yh) {
                __half h[4], l[4];
#pragma unroll
                for (int i = 0; i < 4; i++) split1(v[i], h[i], l[i]);
                *(uint32_t*)(Yh + r0) = *(uint32_t*)&h[0];
                *(uint32_t*)(Yl + r0) = *(uint32_t*)&l[0];
                *(uint32_t*)(Yh + r1) = *(uint32_t*)&h[2];
                *(uint32_t*)(Yl + r1) = *(uint32_t*)&l[2];
            }
        }
}

// ---------------------------------------------------------------------------
// Stage B (warp-per-head, 32-row chunks, grid 1024)
// ---------------------------------------------------------------------------
__global__ void __launch_bounds__(256) stageB_kernel(
    const float* __restrict__ key, const float* __restrict__ value,
    const float* __restrict__ spe, const float* __restrict__ smask,
    float* __restrict__ Kpart, float* __restrict__ KVpart)
{
    const int n = blockIdx.x / SUBC;
    const int chunk = blockIdx.x % SUBC;
    const int s0 = chunk * 32;
    const int h = threadIdx.x >> 5;
    const int lane = threadIdx.x & 31;
    const int c = h * 32 + lane;

    float acc[32];
#pragma unroll
    for (int d = 0; d < 32; d++) acc[d] = 0.f;
    float accKs = 0.f;

    const size_t base = ((size_t)n * SSEQ + s0) * CC;
    const float* mrow = smask + (size_t)n * SSEQ + s0;
    for (int r = 0; r < 32; r++) {
        const size_t row = base + (size_t)r * CC;
        float kc = key[row + c];
        float vc = value[row + c];
        float2 pe = *(const float2*)(spe + (row + c) * 2);
        float m  = mrow[r];
        float kp = __shfl_xor_sync(0xffffffffu, kc, 1);
        float vp = __shfl_xor_sync(0xffffffffu, vc, 1);
        float k2 = (lane & 1) ? kp : -kp;
        float v2 = (lane & 1) ? vp : -vp;
        float Kf   = (kc > 0.f ? kc + 1.f : expf(kc)) * m;
        float Kpos = (kc * pe.x + k2 * pe.y) * m;
        float Vr   = (vc * pe.x + v2 * pe.y) * m;
        accKs += Kf;
#pragma unroll
        for (int d = 0; d < 32; d++) {
            float a = __shfl_sync(0xffffffffu, Kpos, d);
            acc[d] = fmaf(a, Vr, acc[d]);
        }
    }
    Kpart[(size_t)(n*SUBC + chunk)*CC + c] = accKs;
    const size_t kvb = (size_t)(n*SUBC + chunk)*KVSZ + h*1024;
#pragma unroll
    for (int d = 0; d < 32; d++)
        KVpart[kvb + d*32 + lane] = acc[d];
}

// Fixed-order reduction of chunk partials -> Ksum, KV (deterministic)
__global__ void __launch_bounds__(256) reduce_parts(
    const float* __restrict__ Kpart, const float* __restrict__ KVpart,
    float* __restrict__ Ksum, float* __restrict__ KV)
{
    int idx = blockIdx.x * 256 + threadIdx.x;
    if (idx < NB*CC) {
        int n = idx / CC, c = idx % CC;
        float s = 0.f;
        for (int ch = 0; ch < SUBC; ch++)
            s += Kpart[(size_t)(n*SUBC + ch)*CC + c];
        Ksum[idx] = s;
        return;
    }
    int kidx = idx - NB*CC;
    if (kidx < NB*KVSZ) {
        int n = kidx / KVSZ, e = kidx % KVSZ;
        float s = 0.f;
        for (int ch = 0; ch < SUBC; ch++)
            s += KVpart[(size_t)(n*SUBC + ch)*KVSZ + e];
        KV[kidx] = s;
    }
}

// ---------------------------------------------------------------------------
// Stage C (warp-per-head): writes queried directly as fp16 hi/lo
// ---------------------------------------------------------------------------
__global__ void __launch_bounds__(256) stageC_kernel(
    const float* __restrict__ query, const float* __restrict__ xpe,
    const float* __restrict__ xmask, const float* __restrict__ Ksum,
    const float* __restrict__ KV,
    __half* __restrict__ qhi, __half* __restrict__ qlo)
{
    const int n = blockIdx.x / SUBC;
    const int l0 = (blockIdx.x % SUBC) * 32;
    const int h = threadIdx.x >> 5;
    const int lane = threadIdx.x & 31;
    const int c = h * 32 + lane;

    float kvreg[32];
#pragma unroll
    for (int d = 0; d < 32; d++)
        kvreg[d] = KV[(size_t)n*KVSZ + h*1024 + d*32 + lane];
    const float ks = Ksum[n*CC + c];

    const size_t base = ((size_t)n * LQ + l0) * CC;
    const float* mrow = xmask + (size_t)n * LQ + l0;
    for (int r = 0; r < 32; r++) {
        const size_t row = base + (size_t)r * CC;
        float q  = query[row + c];
        float2 pe = *(const float2*)(xpe + (row + c) * 2);
        float m  = mrow[r];
        float qp = __shfl_xor_sync(0xffffffffu, q, 1);
        float q2 = (lane & 1) ? qp : -qp;
        float Qf   = (q > 0.f ? q + 1.f : expf(q)) * m;
        float Qpos = (q * pe.x + q2 * pe.y) * m;

        float p = Qf * ks;
#pragma unroll
        for (int o = 16; o; o >>= 1) p += __shfl_xor_sync(0xffffffffu, p, o);
        float z = 1.f / (p + 1e-6f);

        float out = 0.f;
#pragma unroll
        for (int d = 0; d < 32; d++) {
            float a = __shfl_sync(0xffffffffu, Qpos, d);
            out = fmaf(a, kvreg[d], out);
        }
        out *= z;
        __half hi, lo; split1(out, hi, lo);
        qhi[row + c] = hi;
        qlo[row + c] = lo;
    }
}

// ---------------------------------------------------------------------------
// LayerNorm over last dim (256); one warp per row.
// Writes fp32 (with optional residual) and/or fp16 hi/lo.
// ---------------------------------------------------------------------------
__global__ void __launch_bounds__(256) ln_kernel(
    const float* __restrict__ in, const float* __restrict__ g,
    const float* __restrict__ b, const float* __restrict__ resid,
    float* __restrict__ out, __half* __restrict__ outh, __half* __restrict__ outl)
{
    const int row = blockIdx.x * 8 + (threadIdx.x >> 5);
    const int lane = threadIdx.x & 31;
    const float* p = in + (size_t)row * CC;
    float v[8];
    float s = 0.f;
#pragma unroll
    for (int i = 0; i < 8; i++) { v[i] = p[lane + i*32]; s += v[i]; }
#pragma unroll
    for (int o = 16; o; o >>= 1) s += __shfl_xor_sync(0xffffffffu, s, o);
    float mean = s * (1.f/256.f);
    float s2 = 0.f;
#pragma unroll
    for (int i = 0; i < 8; i++) { float d = v[i] - mean; s2 += d*d; }
#pragma unroll
    for (int o = 16; o; o >>= 1) s2 += __shfl_xor_sync(0xffffffffu, s2, o);
    float rstd = rsqrtf(s2 * (1.f/256.f) + 1e-5f);
#pragma unroll
    for (int i = 0; i < 8; i++) {
        int cch = lane + i*32;
        float o = (v[i] - mean) * rstd * g[cch] + b[cch];
        if (out) {
            float ov = o;
            if (resid) ov += resid[(size_t)row * CC + cch];
            out[(size_t)row * CC + cch] = ov;
        }
        if (outh) {
            __half hi, lo; split1(o, hi, lo);
            outh[(size_t)row * CC + cch] = hi;
            outl[(size_t)row * CC + cch] = lo;
        }
    }
}

// ---------------------------------------------------------------------------
extern "C" void kernel_launch(void* const* d_in, const int* in_sizes, int n_in,
                              void* d_out, int out_size)
{
    const float* x     = (const float*)d_in[0];
    const float* src   = (const float*)d_in[1];
    const float* xpe   = (const float*)d_in[2];
    const float* spe   = (const float*)d_in[3];
    const float* xmask = (const float*)d_in[4];
    const float* smask = (const float*)d_in[5];
    const float* Wq    = (const float*)d_in[6];
    const float* Wk    = (const float*)d_in[7];
    const float* Wv    = (const float*)d_in[8];
    const float* Wm    = (const float*)d_in[9];
    const float* W1    = (const float*)d_in[10];
    const float* W2    = (const float*)d_in[11];
    const float* g1    = (const float*)d_in[12];
    const float* b1    = (const float*)d_in[13];
    const float* g2    = (const float*)d_in[14];
    const float* b2    = (const float*)d_in[15];
    float* out = (float*)d_out;

    float *query, *key, *value, *Kpart, *KVpart, *Ksum, *KV, *msg, *h2;
    __half *xhi, *xlo, *shi, *slo, *qhi, *qlo, *m1hi, *m1lo, *hbhi, *hblo, *wh;
    cudaGetSymbolAddress((void**)&query,  g_query);
    cudaGetSymbolAddress((void**)&key,    g_key);
    cudaGetSymbolAddress((void**)&value,  g_value);
    cudaGetSymbolAddress((void**)&Kpart,  g_Kpart);
    cudaGetSymbolAddress((void**)&KVpart, g_KVpart);
    cudaGetSymbolAddress((void**)&Ksum,   g_Ksum);
    cudaGetSymbolAddress((void**)&KV,     g_KV);
    cudaGetSymbolAddress((void**)&msg,    g_msg);
    cudaGetSymbolAddress((void**)&h2,     g_h2);
    cudaGetSymbolAddress((void**)&xhi,  g_xhi);  cudaGetSymbolAddress((void**)&xlo,  g_xlo);
    cudaGetSymbolAddress((void**)&shi,  g_shi);  cudaGetSymbolAddress((void**)&slo,  g_slo);
    cudaGetSymbolAddress((void**)&qhi,  g_qhi);  cudaGetSymbolAddress((void**)&qlo,  g_qlo);
    cudaGetSymbolAddress((void**)&m1hi, g_m1hi); cudaGetSymbolAddress((void**)&m1lo, g_m1lo);
    cudaGetSymbolAddress((void**)&hbhi, g_hbhi); cudaGetSymbolAddress((void**)&hblo, g_hblo);
    cudaGetSymbolAddress((void**)&wh,   g_wh);

    cudaFuncSetAttribute(hgemm, cudaFuncAttributeMaxDynamicSharedMemorySize, SMEM_DYN);

    const int BIG = 1 << 30;
    dim3 gN256(CC / BN, MTOT / BM);         // (2, 512)
    dim3 gN512(2*CC / BN, MTOT / BM);       // (4, 512)

    // One-time converts
    convert_w<<<WH_TOT/4/256, 256>>>(Wq, Wk, Wv, Wm, W1, W2, wh);
    convert_act<<<MTOT*CC/4/256, 256>>>(x,   xhi, xlo, MTOT*CC/4);
    convert_act<<<MSRC*CC/4/256, 256>>>(src, shi, slo, MSRC*CC/4);

    // QKV projections (A row stride = CC)
    hgemm<<<gN256, 256, SMEM_DYN>>>(xhi, xlo, xhi, xlo, BIG, CC, wh + WH_Q,
                                    query, nullptr, nullptr, CC, CC, 0);
    hgemm<<<gN256, 256, SMEM_DYN>>>(shi, slo, shi, slo, BIG, CC, wh + WH_K,
                                    key,   nullptr, nullptr, CC, CC, 0);
    hgemm<<<gN256, 256, SMEM_DYN>>>(shi, slo, shi, slo, BIG, CC, wh + WH_V,
                                    value, nullptr, nullptr, CC, CC, 0);

    // Linear-attention KV / Ksum (deterministic two-stage reduction)
    stageB_kernel<<<NB*SUBC, 256>>>(key, value, spe, smask, Kpart, KVpart);
    reduce_parts<<<(NB*CC + NB*KVSZ + 255) / 256, 256>>>(Kpart, KVpart, Ksum, KV);

    // Q-side: Z + queried (fp16 hi/lo out)
    stageC_kernel<<<NB*SUBC, 256>>>(query, xpe, xmask, Ksum, KV, qhi, qlo);

    // Message projection + LN1 (m1 as fp16 hi/lo)
    hgemm<<<gN256, 256, SMEM_DYN>>>(qhi, qlo, qhi, qlo, BIG, CC, wh + WH_M,
                                    msg, nullptr, nullptr, CC, CC, 0);
    ln_kernel<<<MTOT/8, 256>>>(msg, g1, b1, nullptr, nullptr, m1hi, m1lo);

    // MLP: h = relu([x, m1] @ W1^T) -> fp16 hi/lo; h2 = h @ W2^T -> fp32
    // A row stride = CC for both x and m1 halves; K (W row stride) = 2*CC.
    hgemm<<<gN512, 256, SMEM_DYN>>>(xhi, xlo, m1hi, m1lo, CC, CC, wh + WH_1,
                                    nullptr, hbhi, hblo, 2*CC, 2*CC, 1);
    hgemm<<<gN256, 256, SMEM_DYN>>>(hbhi, hblo, hbhi, hblo, BIG, 2*CC, wh + WH_2,
                                    h2, nullptr, nullptr, CC, 2*CC, 0);

    // out = x + LN2(h2)
    ln_kernel<<<MTOT/8, 256>>>(h2, g2, b2, x, out, nullptr, nullptr);
}

// round 9
// speedup vs baseline: 3.8047x; 1.0874x over previous
#include <cuda_runtime.h>
#include <cuda_fp16.h>
#include <math.h>
#include <stdint.h>

// Problem constants
#define NB 4
#define LQ 8192
#define SSEQ 8192
#define CC 256
#define HH 8
#define DD 32
#define MTOT (NB*LQ)     // 32768 query rows
#define MSRC (NB*SSEQ)   // 32768 source rows
#define SUBC 256         // 32-row chunks per batch
#define KVSZ (HH*DD*DD)  // 8192 per batch

// fp16 weight arena segment offsets (halves)
#define WH_Q  0
#define WH_K  65536      // Wk rows 0..255 then Wv rows 256..511 (contiguous => merged)
#define WH_V  131072
#define WH_M  196608
#define WH_1  262144
#define WH_2  524288
#define WH_TOT 655360

// Scratch (device globals: no allocation allowed)
__device__ float g_query[MTOT*CC];
__device__ float g_kv[(size_t)MSRC*2*CC];     // merged key|value, row stride 512
__device__ float g_Kpart[(size_t)NB*SUBC*CC];
__device__ float g_KVpart[(size_t)NB*SUBC*KVSZ];
__device__ float g_Ksum[NB*CC];
__device__ float g_KV[NB*KVSZ];
__device__ float g_msg[MTOT*CC];
__device__ float g_h2[MTOT*CC];
// fp16 hi/lo activation tensors
__device__ __half g_xhi[MTOT*CC],  g_xlo[MTOT*CC];
__device__ __half g_shi[MSRC*CC],  g_slo[MSRC*CC];
__device__ __half g_qhi[MTOT*CC],  g_qlo[MTOT*CC];      // queried
__device__ __half g_m1hi[MTOT*CC], g_m1lo[MTOT*CC];
__device__ __half g_hbhi[(size_t)MTOT*2*CC], g_hblo[(size_t)MTOT*2*CC];
__device__ __half g_wh[WH_TOT];

// ===========================================================================
// Helpers
// ===========================================================================
__device__ __forceinline__ uint32_t smem_u32(const void* p) {
    uint32_t a;
    asm("{ .reg .u64 t; cvta.to.shared.u64 t, %1; cvt.u32.u64 %0, t; }"
        : "=r"(a) : "l"(p));
    return a;
}
__device__ __forceinline__ void split1(float v, __half& hi, __half& lo) {
    hi = __float2half_rn(v);
    lo = __float2half_rn(v - __half2float(hi));
}

#define CP_ASYNC16(dst_u32, src_ptr) \
    asm volatile("cp.async.cg.shared.global [%0], [%1], 16;" \
        :: "r"(dst_u32), "l"(src_ptr))
#define CP_COMMIT() asm volatile("cp.async.commit_group;")
#define CP_WAIT1()  asm volatile("cp.async.wait_group 1;")

#define LDSM_X4(r0,r1,r2,r3, addr) \
    asm volatile("ldmatrix.sync.aligned.m8n8.x4.shared.b16 {%0,%1,%2,%3}, [%4];" \
        : "=r"(r0), "=r"(r1), "=r"(r2), "=r"(r3) : "r"(addr))
#define LDSM_X2(r0,r1, addr) \
    asm volatile("ldmatrix.sync.aligned.m8n8.x2.shared.b16 {%0,%1}, [%2];" \
        : "=r"(r0), "=r"(r1) : "r"(addr))

__device__ __forceinline__ void mma16816(float* c, const uint32_t* a, const uint32_t* b) {
    asm volatile(
        "mma.sync.aligned.m16n8k16.row.col.f32.f16.f16.f32 "
        "{%0,%1,%2,%3}, {%4,%5,%6,%7}, {%8,%9}, {%0,%1,%2,%3};"
        : "+f"(c[0]), "+f"(c[1]), "+f"(c[2]), "+f"(c[3])
        : "r"(a[0]), "r"(a[1]), "r"(a[2]), "r"(a[3]), "r"(b[0]), "r"(b[1]));
}

// ===========================================================================
// One-time converts
// ===========================================================================
__global__ void convert_act(const float* __restrict__ in,
                            __half* __restrict__ hi, __half* __restrict__ lo, int n4)
{
    int i = blockIdx.x * 256 + threadIdx.x;
    if (i >= n4) return;
    float4 v = ((const float4*)in)[i];
    __half h[4], l[4];
    split1(v.x, h[0], l[0]); split1(v.y, h[1], l[1]);
    split1(v.z, h[2], l[2]); split1(v.w, h[3], l[3]);
    ((uint2*)hi)[i] = *(uint2*)h;
    ((uint2*)lo)[i] = *(uint2*)l;
}

__global__ void convert_w(const float* __restrict__ Wq, const float* __restrict__ Wk,
                          const float* __restrict__ Wv, const float* __restrict__ Wm,
                          const float* __restrict__ W1, const float* __restrict__ W2,
                          __half* __restrict__ arena)
{
    int idx = (blockIdx.x * 256 + threadIdx.x) * 4;
    if (idx >= WH_TOT) return;
    const float* src; int off;
    if (idx < WH_1) {
        int seg = idx >> 16;
        src = (seg == 0) ? Wq : (seg == 1) ? Wk : (seg == 2) ? Wv : Wm;
        off = idx & 65535;
    } else if (idx < WH_2) { src = W1; off = idx - WH_1; }
    else                   { src = W2; off = idx - WH_2; }
    float4 v = *(const float4*)(src + off);
    __half h[4] = {__float2half_rn(v.x), __float2half_rn(v.y),
                   __float2half_rn(v.z), __float2half_rn(v.w)};
    *(uint2*)(arena + idx) = *(uint2*)h;
}

// ===========================================================================
// Tensor-core GEMM, cp.async 3-stage pipeline, fully unrolled mainloop:
//   Y[m,n] = act( sum_k (Ah+Al)[m,k] * Bh[n,k] )
// Tile 64x128xBK32, 256 threads / 8 warps (warp tile 32x32), 3 CTAs/SM.
// Template NK = K/32 (fully unrolls), SPLIT = concat-A (W1 GEMM).
// ===========================================================================
#define BM 64
#define BN 128
#define BK 32
#define STAGES 3
#define SSTR 40                 // padded fp16 row stride (80B): conflict-free ldmatrix
#define SA (64*SSTR*2)          // 5120 B per A tile (hi or lo)
#define SB (128*SSTR*2)         // 10240 B (Bh)
#define STG (2*SA + SB)         // 20480
#define SMEM_DYN (STAGES*STG)   // 61440

template<int NK, bool SPLIT>
__global__ void __launch_bounds__(256, 3) hgemm(
    const __half* __restrict__ Ah, const __half* __restrict__ Al,
    const __half* __restrict__ A2h, const __half* __restrict__ A2l,
    int Ksplit, int lda, const __half* __restrict__ W,
    float* __restrict__ Y, __half* __restrict__ Yh, __half* __restrict__ Yl,
    int Nn, int relu)
{
    constexpr int K = NK * BK;
    extern __shared__ __align__(16) char smem[];
    const uint32_t sb = smem_u32(smem);

    const int tid = threadIdx.x;
    const int lane = tid & 31;
    const int wid = tid >> 5;
    const int bm = blockIdx.y * BM;
    const int bn = blockIdx.x * BN;
    const int wm = (wid >> 2) * 32;
    const int wn = (wid & 3) * 32;

    // loader mapping: 16B = 8 halves per cp.async
    const int arow = tid >> 2;          // 0..63
    const int acol = (tid & 3) * 8;     // 0,8,16,24
    const uint32_t sAoff = (uint32_t)(arow * SSTR + acol) * 2;

    // issue loads for chunk ck into stage st
    auto load_chunk = [&](int ck, int st) {
        const int k0 = ck * BK;
        const __half* ah = Ah; const __half* al = Al;
        int kk0 = k0;
        if (SPLIT && k0 >= Ksplit) { ah = A2h; al = A2l; kk0 = k0 - Ksplit; }
        const uint32_t base = sb + st * STG;
        CP_ASYNC16(base + sAoff,      ah + (size_t)(bm + arow) * lda + kk0 + acol);
        CP_ASYNC16(base + SA + sAoff, al + (size_t)(bm + arow) * lda + kk0 + acol);
        CP_ASYNC16(base + 2*SA + sAoff,
                   W + (size_t)(bn + arow) * K + k0 + acol);
        CP_ASYNC16(base + 2*SA + sAoff + (uint32_t)(64 * SSTR * 2),
                   W + (size_t)(bn + 64 + arow) * K + k0 + acol);
    };

    float c[2][4][4];
#pragma unroll
    for (int mi = 0; mi < 2; mi++)
#pragma unroll
        for (int ni = 0; ni < 4; ni++)
#pragma unroll
            for (int i = 0; i < 4; i++) c[mi][ni][i] = 0.f;

    load_chunk(0, 0); CP_COMMIT();
    load_chunk(1, 1); CP_COMMIT();

#pragma unroll
    for (int ck = 0; ck < NK; ck++) {
        CP_WAIT1();
        __syncthreads();   // single barrier per iter: orders mma(ck-1) of all
                           // warps before slot-of-(ck-1) is overwritten below

        const int nc = ck + STAGES - 1;
        if (nc < NK) load_chunk(nc, nc % STAGES);
        CP_COMMIT();

        const uint32_t sAh = sb + (ck % STAGES) * STG;
        const uint32_t sAl = sAh + SA;
        const uint32_t sBh = sAh + 2*SA;
#pragma unroll
        for (int kk = 0; kk < 2; kk++) {
            uint32_t ahf[2][4], alf[2][4], bhf[4][2];
            const uint32_t aoff =
                ((wm + (lane & 15)) * SSTR + kk * 16 + (lane >> 4) * 8) * 2;
#pragma unroll
            for (int mi = 0; mi < 2; mi++) {
                LDSM_X4(ahf[mi][0], ahf[mi][1], ahf[mi][2], ahf[mi][3],
                        sAh + aoff + mi * 16 * SSTR * 2);
                LDSM_X4(alf[mi][0], alf[mi][1], alf[mi][2], alf[mi][3],
                        sAl + aoff + mi * 16 * SSTR * 2);
            }
            const uint32_t boff =
                ((wn + (lane & 7)) * SSTR + kk * 16 + ((lane >> 3) & 1) * 8) * 2;
#pragma unroll
            for (int ni = 0; ni < 4; ni++)
                LDSM_X2(bhf[ni][0], bhf[ni][1], sBh + boff + ni * 8 * SSTR * 2);
#pragma unroll
            for (int mi = 0; mi < 2; mi++)
#pragma unroll
                for (int ni = 0; ni < 4; ni++) {
                    mma16816(c[mi][ni], ahf[mi], bhf[ni]);
                    mma16816(c[mi][ni], alf[mi], bhf[ni]);
                }
        }
    }

    // Epilogue: c frag mapping (m16n8): rows lane/4 (+8), cols (lane%4)*2 (+1)
    const int grp = lane >> 2;
    const int tg = (lane & 3) * 2;
#pragma unroll
    for (int mi = 0; mi < 2; mi++)
#pragma unroll
        for (int ni = 0; ni < 4; ni++) {
            float v[4] = {c[mi][ni][0], c[mi][ni][1], c[mi][ni][2], c[mi][ni][3]};
            if (relu) {
#pragma unroll
                for (int i = 0; i < 4; i++) v[i] = fmaxf(v[i], 0.f);
            }
            const size_t r0 = (size_t)(bm + wm + mi * 16 + grp) * Nn + bn + wn + ni * 8 + tg;
            const size_t r1 = r0 + (size_t)8 * Nn;
            if (Y) {
                *(float2*)(Y + r0) = make_float2(v[0], v[1]);
                *(float2*)(Y + r1) = make_float2(v[2], v[3]);
            }
            if (Yh) {
                __half h[4], l[4];
#pragma unroll
                for (int i = 0; i < 4; i++) split1(v[i], h[i], l[i]);
                *(uint32_t*)(Yh + r0) = *(uint32_t*)&h[0];
                *(uint32_t*)(Yl + r0) = *(uint32_t*)&l[0];
                *(uint32_t*)(Yh + r1) = *(uint32_t*)&h[2];
                *(uint32_t*)(Yl + r1) = *(uint32_t*)&l[2];
            }
        }
}

// ---------------------------------------------------------------------------
// Stage B (warp-per-head, 32-row chunks, grid 1024); reads merged kv buffer
// (row stride 512: key at col c, value at col 256+c).
// ---------------------------------------------------------------------------
__global__ void __launch_bounds__(256) stageB_kernel(
    const float* __restrict__ kvbuf,
    const float* __restrict__ spe, const float* __restrict__ smask,
    float* __restrict__ Kpart, float* __restrict__ KVpart)
{
    const int n = blockIdx.x / SUBC;
    const int chunk = blockIdx.x % SUBC;
    const int s0 = chunk * 32;
    const int h = threadIdx.x >> 5;
    const int lane = threadIdx.x & 31;
    const int c = h * 32 + lane;

    float acc[32];
#pragma unroll
    for (int d = 0; d < 32; d++) acc[d] = 0.f;
    float accKs = 0.f;

    const size_t pebase = ((size_t)n * SSEQ + s0) * CC;
    const size_t kvbase = ((size_t)n * SSEQ + s0) * (2*CC);
    const float* mrow = smask + (size_t)n * SSEQ + s0;
    for (int r = 0; r < 32; r++) {
        const size_t kvrow = kvbase + (size_t)r * (2*CC);
        float kc = kvbuf[kvrow + c];
        float vc = kvbuf[kvrow + CC + c];
        float2 pe = *(const float2*)(spe + (pebase + (size_t)r * CC + c) * 2);
        float m  = mrow[r];
        float kp = __shfl_xor_sync(0xffffffffu, kc, 1);
        float vp = __shfl_xor_sync(0xffffffffu, vc, 1);
        float k2 = (lane & 1) ? kp : -kp;
        float v2 = (lane & 1) ? vp : -vp;
        float Kf   = (kc > 0.f ? kc + 1.f : expf(kc)) * m;
        float Kpos = (kc * pe.x + k2 * pe.y) * m;
        float Vr   = (vc * pe.x + v2 * pe.y) * m;
        accKs += Kf;
#pragma unroll
        for (int d = 0; d < 32; d++) {
            float a = __shfl_sync(0xffffffffu, Kpos, d);
            acc[d] = fmaf(a, Vr, acc[d]);
        }
    }
    Kpart[(size_t)(n*SUBC + chunk)*CC + c] = accKs;
    const size_t kvb = (size_t)(n*SUBC + chunk)*KVSZ + h*1024;
#pragma unroll
    for (int d = 0; d < 32; d++)
        KVpart[kvb + d*32 + lane] = acc[d];
}

// Fixed-order reduction of chunk partials -> Ksum, KV (deterministic)
__global__ void __launch_bounds__(256) reduce_parts(
    const float* __restrict__ Kpart, const float* __restrict__ KVpart,
    float* __restrict__ Ksum, float* __restrict__ KV)
{
    int idx = blockIdx.x * 256 + threadIdx.x;
    if (idx < NB*CC) {
        int n = idx / CC, c = idx % CC;
        float s = 0.f;
        for (int ch = 0; ch < SUBC; ch++)
            s += Kpart[(size_t)(n*SUBC + ch)*CC + c];
        Ksum[idx] = s;
        return;
    }
    int kidx = idx - NB*CC;
    if (kidx < NB*KVSZ) {
        int n = kidx / KVSZ, e = kidx % KVSZ;
        float s = 0.f;
        for (int ch = 0; ch < SUBC; ch++)
            s += KVpart[(size_t)(n*SUBC + ch)*KVSZ + e];
        KV[kidx] = s;
    }
}

// ---------------------------------------------------------------------------
// Stage C (warp-per-head): writes queried directly as fp16 hi/lo
// ---------------------------------------------------------------------------
__global__ void __launch_bounds__(256) stageC_kernel(
    const float* __restrict__ query, const float* __restrict__ xpe,
    const float* __restrict__ xmask, const float* __restrict__ Ksum,
    const float* __restrict__ KV,
    __half* __restrict__ qhi, __half* __restrict__ qlo)
{
    const int n = blockIdx.x / SUBC;
    const int l0 = (blockIdx.x % SUBC) * 32;
    const int h = threadIdx.x >> 5;
    const int lane = threadIdx.x & 31;
    const int c = h * 32 + lane;

    float kvreg[32];
#pragma unroll
    for (int d = 0; d < 32; d++)
        kvreg[d] = KV[(size_t)n*KVSZ + h*1024 + d*32 + lane];
    const float ks = Ksum[n*CC + c];

    const size_t base = ((size_t)n * LQ + l0) * CC;
    const float* mrow = xmask + (size_t)n * LQ + l0;
    for (int r = 0; r < 32; r++) {
        const size_t row = base + (size_t)r * CC;
        float q  = query[row + c];
        float2 pe = *(const float2*)(xpe + (row + c) * 2);
        float m  = mrow[r];
        float qp = __shfl_xor_sync(0xffffffffu, q, 1);
        float q2 = (lane & 1) ? qp : -qp;
        float Qf   = (q > 0.f ? q + 1.f : expf(q)) * m;
        float Qpos = (q * pe.x + q2 * pe.y) * m;

        float p = Qf * ks;
#pragma unroll
        for (int o = 16; o; o >>= 1) p += __shfl_xor_sync(0xffffffffu, p, o);
        float z = 1.f / (p + 1e-6f);

        float out = 0.f;
#pragma unroll
        for (int d = 0; d < 32; d++) {
            float a = __shfl_sync(0xffffffffu, Qpos, d);
            out = fmaf(a, kvreg[d], out);
        }
        out *= z;
        __half hi, lo; split1(out, hi, lo);
        qhi[row + c] = hi;
        qlo[row + c] = lo;
    }
}

// ---------------------------------------------------------------------------
// LayerNorm over last dim (256); one warp per row.
// Writes fp32 (with optional residual) and/or fp16 hi/lo.
// ---------------------------------------------------------------------------
__global__ void __launch_bounds__(256) ln_kernel(
    const float* __restrict__ in, const float* __restrict__ g,
    const float* __restrict__ b, const float* __restrict__ resid,
    float* __restrict__ out, __half* __restrict__ outh, __half* __restrict__ outl)
{
    const int row = blockIdx.x * 8 + (threadIdx.x >> 5);
    const int lane = threadIdx.x & 31;
    const float* p = in + (size_t)row * CC;
    float v[8];
    float s = 0.f;
#pragma unroll
    for (int i = 0; i < 8; i++) { v[i] = p[lane + i*32]; s += v[i]; }
#pragma unroll
    for (int o = 16; o; o >>= 1) s += __shfl_xor_sync(0xffffffffu, s, o);
    float mean = s * (1.f/256.f);
    float s2 = 0.f;
#pragma unroll
    for (int i = 0; i < 8; i++) { float d = v[i] - mean; s2 += d*d; }
#pragma unroll
    for (int o = 16; o; o >>= 1) s2 += __shfl_xor_sync(0xffffffffu, s2, o);
    float rstd = rsqrtf(s2 * (1.f/256.f) + 1e-5f);
#pragma unroll
    for (int i = 0; i < 8; i++) {
        int cch = lane + i*32;
        float o = (v[i] - mean) * rstd * g[cch] + b[cch];
        if (out) {
            float ov = o;
            if (resid) ov += resid[(size_t)row * CC + cch];
            out[(size_t)row * CC + cch] = ov;
        }
        if (outh) {
            __half hi, lo; split1(o, hi, lo);
            outh[(size_t)row * CC + cch] = hi;
            outl[(size_t)row * CC + cch] = lo;
        }
    }
}

// ---------------------------------------------------------------------------
extern "C" void kernel_launch(void* const* d_in, const int* in_sizes, int n_in,
                              void* d_out, int out_size)
{
    const float* x     = (const float*)d_in[0];
    const float* src   = (const float*)d_in[1];
    const float* xpe   = (const float*)d_in[2];
    const float* spe   = (const float*)d_in[3];
    const float* xmask = (const float*)d_in[4];
    const float* smask = (const float*)d_in[5];
    const float* Wq    = (const float*)d_in[6];
    const float* Wk    = (const float*)d_in[7];
    const float* Wv    = (const float*)d_in[8];
    const float* Wm    = (const float*)d_in[9];
    const float* W1    = (const float*)d_in[10];
    const float* W2    = (const float*)d_in[11];
    const float* g1    = (const float*)d_in[12];
    const float* b1    = (const float*)d_in[13];
    const float* g2    = (const float*)d_in[14];
    const float* b2    = (const float*)d_in[15];
    float* out = (float*)d_out;

    float *query, *kvbuf, *Kpart, *KVpart, *Ksum, *KV, *msg, *h2;
    __half *xhi, *xlo, *shi, *slo, *qhi, *qlo, *m1hi, *m1lo, *hbhi, *hblo, *wh;
    cudaGetSymbolAddress((void**)&query,  g_query);
    cudaGetSymbolAddress((void**)&kvbuf,  g_kv);
    cudaGetSymbolAddress((void**)&Kpart,  g_Kpart);
    cudaGetSymbolAddress((void**)&KVpart, g_KVpart);
    cudaGetSymbolAddress((void**)&Ksum,   g_Ksum);
    cudaGetSymbolAddress((void**)&KV,     g_KV);
    cudaGetSymbolAddress((void**)&msg,    g_msg);
    cudaGetSymbolAddress((void**)&h2,     g_h2);
    cudaGetSymbolAddress((void**)&xhi,  g_xhi);  cudaGetSymbolAddress((void**)&xlo,  g_xlo);
    cudaGetSymbolAddress((void**)&shi,  g_shi);  cudaGetSymbolAddress((void**)&slo,  g_slo);
    cudaGetSymbolAddress((void**)&qhi,  g_qhi);  cudaGetSymbolAddress((void**)&qlo,  g_qlo);
    cudaGetSymbolAddress((void**)&m1hi, g_m1hi); cudaGetSymbolAddress((void**)&m1lo, g_m1lo);
    cudaGetSymbolAddress((void**)&hbhi, g_hbhi); cudaGetSymbolAddress((void**)&hblo, g_hblo);
    cudaGetSymbolAddress((void**)&wh,   g_wh);

    cudaFuncSetAttribute(hgemm<8,false>,  cudaFuncAttributeMaxDynamicSharedMemorySize, SMEM_DYN);
    cudaFuncSetAttribute(hgemm<16,true>,  cudaFuncAttributeMaxDynamicSharedMemorySize, SMEM_DYN);
    cudaFuncSetAttribute(hgemm<16,false>, cudaFuncAttributeMaxDynamicSharedMemorySize, SMEM_DYN);

    const int BIG = 1 << 30;
    dim3 gQ(CC / BN, MTOT / BM);            // (2, 512) N=256
    dim3 gKV(2*CC / BN, MSRC / BM);         // (4, 512) merged N=512
    dim3 gW1(2*CC / BN, MTOT / BM);         // (4, 512)

    // One-time converts
    convert_w<<<WH_TOT/4/256, 256>>>(Wq, Wk, Wv, Wm, W1, W2, wh);
    convert_act<<<MTOT*CC/4/256, 256>>>(x,   xhi, xlo, MTOT*CC/4);
    convert_act<<<MSRC*CC/4/256, 256>>>(src, shi, slo, MSRC*CC/4);

    // Q projection; merged K|V projection (weight arena rows 0..511 = Wk|Wv)
    hgemm<8,false><<<gQ, 256, SMEM_DYN>>>(xhi, xlo, xhi, xlo, BIG, CC, wh + WH_Q,
                                          query, nullptr, nullptr, CC, 0);
    hgemm<8,false><<<gKV, 256, SMEM_DYN>>>(shi, slo, shi, slo, BIG, CC, wh + WH_K,
                                           kvbuf, nullptr, nullptr, 2*CC, 0);

    // Linear-attention KV / Ksum (deterministic two-stage reduction)
    stageB_kernel<<<NB*SUBC, 256>>>(kvbuf, spe, smask, Kpart, KVpart);
    reduce_parts<<<(NB*CC + NB*KVSZ + 255) / 256, 256>>>(Kpart, KVpart, Ksum, KV);

    // Q-side: Z + queried (fp16 hi/lo out)
    stageC_kernel<<<NB*SUBC, 256>>>(query, xpe, xmask, Ksum, KV, qhi, qlo);

    // Message projection + LN1 (m1 as fp16 hi/lo)
    hgemm<8,false><<<gQ, 256, SMEM_DYN>>>(qhi, qlo, qhi, qlo, BIG, CC, wh + WH_M,
                                          msg, nullptr, nullptr, CC, 0);
    ln_kernel<<<MTOT/8, 256>>>(msg, g1, b1, nullptr, nullptr, m1hi, m1lo);

    // MLP: h = relu([x, m1] @ W1^T) -> fp16 hi/lo; h2 = h @ W2^T -> fp32
    hgemm<16,true><<<gW1, 256, SMEM_DYN>>>(xhi, xlo, m1hi, m1lo, CC, CC, wh + WH_1,
                                           nullptr, hbhi, hblo, 2*CC, 1);
    hgemm<16,false><<<gQ, 256, SMEM_DYN>>>(hbhi, hblo, hbhi, hblo, BIG, 2*CC, wh + WH_2,
                                           h2, nullptr, nullptr, CC, 0);

    // out = x + LN2(h2)
    ln_kernel<<<MTOT/8, 256>>>(h2, g2, b2, x, out, nullptr, nullptr);
}

// round 10
// speedup vs baseline: 4.7328x; 1.2439x over previous
#include <cuda_runtime.h>
#include <cuda_fp16.h>
#include <math.h>
#include <stdint.h>

// Problem constants
#define NB 4
#define LQ 8192
#define SSEQ 8192
#define CC 256
#define HH 8
#define DD 32
#define MTOT (NB*LQ)     // 32768 query rows
#define MSRC (NB*SSEQ)   // 32768 source rows
#define SUBC 256         // 32-row chunks per batch
#define KVSZ (HH*DD*DD)  // 8192 per batch

// fp16 weight arena segment offsets (halves)
#define WH_Q  0
#define WH_K  65536      // Wk rows 0..255 then Wv rows 256..511 (contiguous => merged)
#define WH_M  196608
#define WH_1  262144
#define WH_2  524288
#define WH_TOT 655360

// Scratch (device globals: no allocation allowed)
__device__ float g_query[MTOT*CC];
__device__ float g_kv[(size_t)MSRC*2*CC];     // merged key|value, row stride 512
__device__ float g_Kpart[(size_t)NB*SUBC*CC];
__device__ float g_KVpart[(size_t)NB*SUBC*KVSZ];
__device__ float g_Ksum[NB*CC];
__device__ float g_KV[NB*KVSZ];
__device__ float g_msg[MTOT*CC];
__device__ float g_h2[MTOT*CC];
// fp16 activation tensors (single-term)
__device__ __half g_xh[MTOT*CC];
__device__ __half g_sh[MSRC*CC];
__device__ __half g_qh[MTOT*CC];       // queried
__device__ __half g_m1h[MTOT*CC];
__device__ __half g_hbh[(size_t)MTOT*2*CC];
__device__ __half g_wh[WH_TOT];

// ===========================================================================
// Helpers
// ===========================================================================
__device__ __forceinline__ uint32_t smem_u32(const void* p) {
    uint32_t a;
    asm("{ .reg .u64 t; cvta.to.shared.u64 t, %1; cvt.u32.u64 %0, t; }"
        : "=r"(a) : "l"(p));
    return a;
}

#define CP_ASYNC16(dst_u32, src_ptr) \
    asm volatile("cp.async.cg.shared.global [%0], [%1], 16;" \
        :: "r"(dst_u32), "l"(src_ptr))
#define CP_COMMIT() asm volatile("cp.async.commit_group;")
#define CP_WAIT1()  asm volatile("cp.async.wait_group 1;")

#define LDSM_X4(r0,r1,r2,r3, addr) \
    asm volatile("ldmatrix.sync.aligned.m8n8.x4.shared.b16 {%0,%1,%2,%3}, [%4];" \
        : "=r"(r0), "=r"(r1), "=r"(r2), "=r"(r3) : "r"(addr))
#define LDSM_X2(r0,r1, addr) \
    asm volatile("ldmatrix.sync.aligned.m8n8.x2.shared.b16 {%0,%1}, [%2];" \
        : "=r"(r0), "=r"(r1) : "r"(addr))

__device__ __forceinline__ void mma16816(float* c, const uint32_t* a, const uint32_t* b) {
    asm volatile(
        "mma.sync.aligned.m16n8k16.row.col.f32.f16.f16.f32 "
        "{%0,%1,%2,%3}, {%4,%5,%6,%7}, {%8,%9}, {%0,%1,%2,%3};"
        : "+f"(c[0]), "+f"(c[1]), "+f"(c[2]), "+f"(c[3])
        : "r"(a[0]), "r"(a[1]), "r"(a[2]), "r"(a[3]), "r"(b[0]), "r"(b[1]));
}

// ===========================================================================
// One-time converts (round-to-nearest fp16)
// ===========================================================================
__global__ void convert_act(const float* __restrict__ in,
                            __half* __restrict__ hi, int n4)
{
    int i = blockIdx.x * 256 + threadIdx.x;
    if (i >= n4) return;
    float4 v = ((const float4*)in)[i];
    __half h[4] = {__float2half_rn(v.x), __float2half_rn(v.y),
                   __float2half_rn(v.z), __float2half_rn(v.w)};
    ((uint2*)hi)[i] = *(uint2*)h;
}

__global__ void convert_w(const float* __restrict__ Wq, const float* __restrict__ Wk,
                          const float* __restrict__ Wv, const float* __restrict__ Wm,
                          const float* __restrict__ W1, const float* __restrict__ W2,
                          __half* __restrict__ arena)
{
    int idx = (blockIdx.x * 256 + threadIdx.x) * 4;
    if (idx >= WH_TOT) return;
    const float* src; int off;
    if (idx < WH_1) {
        int seg = idx >> 16;
        src = (seg == 0) ? Wq : (seg == 1) ? Wk : (seg == 2) ? Wv : Wm;
        off = idx & 65535;
    } else if (idx < WH_2) { src = W1; off = idx - WH_1; }
    else                   { src = W2; off = idx - WH_2; }
    float4 v = *(const float4*)(src + off);
    __half h[4] = {__float2half_rn(v.x), __float2half_rn(v.y),
                   __float2half_rn(v.z), __float2half_rn(v.w)};
    *(uint2*)(arena + idx) = *(uint2*)h;
}

// ===========================================================================
// Tensor-core GEMM, cp.async 3-stage pipeline, single-term fp16:
//   Y[m,n] = act( sum_k Ah[m,k] * Bh[n,k] )
// Tile 64x128xBK32, 256 threads / 8 warps (warp tile 32x32), 4 CTAs/SM.
// Template NK = K/32 (fully unrolls), SPLIT = concat-A (W1 GEMM).
// ===========================================================================
#define BM 64
#define BN 128
#define BK 32
#define STAGES 3
#define SSTR 40                 // padded fp16 row stride (80B): conflict-free ldmatrix
#define SA (64*SSTR*2)          // 5120 B (A tile)
#define SB (128*SSTR*2)         // 10240 B (B tile)
#define STG (SA + SB)           // 15360
#define SMEM_DYN (STAGES*STG)   // 46080

template<int NK, bool SPLIT>
__global__ void __launch_bounds__(256, 4) hgemm(
    const __half* __restrict__ Ah, const __half* __restrict__ A2h,
    int Ksplit, int lda, const __half* __restrict__ W,
    float* __restrict__ Y, __half* __restrict__ Yh,
    int Nn, int relu)
{
    constexpr int K = NK * BK;
    extern __shared__ __align__(16) char smem[];
    const uint32_t sb = smem_u32(smem);

    const int tid = threadIdx.x;
    const int lane = tid & 31;
    const int wid = tid >> 5;
    const int bm = blockIdx.y * BM;
    const int bn = blockIdx.x * BN;
    const int wm = (wid >> 2) * 32;
    const int wn = (wid & 3) * 32;

    // loader mapping: 16B = 8 halves per cp.async
    const int arow = tid >> 2;          // 0..63
    const int acol = (tid & 3) * 8;     // 0,8,16,24
    const uint32_t sAoff = (uint32_t)(arow * SSTR + acol) * 2;

    // issue loads for chunk ck into stage st
    auto load_chunk = [&](int ck, int st) {
        const int k0 = ck * BK;
        const __half* ah = Ah;
        int kk0 = k0;
        if (SPLIT && k0 >= Ksplit) { ah = A2h; kk0 = k0 - Ksplit; }
        const uint32_t base = sb + st * STG;
        CP_ASYNC16(base + sAoff, ah + (size_t)(bm + arow) * lda + kk0 + acol);
        CP_ASYNC16(base + SA + sAoff,
                   W + (size_t)(bn + arow) * K + k0 + acol);
        CP_ASYNC16(base + SA + sAoff + (uint32_t)(64 * SSTR * 2),
                   W + (size_t)(bn + 64 + arow) * K + k0 + acol);
    };

    float c[2][4][4];
#pragma unroll
    for (int mi = 0; mi < 2; mi++)
#pragma unroll
        for (int ni = 0; ni < 4; ni++)
#pragma unroll
            for (int i = 0; i < 4; i++) c[mi][ni][i] = 0.f;

    load_chunk(0, 0); CP_COMMIT();
    load_chunk(1, 1); CP_COMMIT();

#pragma unroll
    for (int ck = 0; ck < NK; ck++) {
        CP_WAIT1();
        __syncthreads();   // single barrier per iter: orders mma(ck-1) of all
                           // warps before slot-of-(ck-1) is overwritten below

        const int nc = ck + STAGES - 1;
        if (nc < NK) load_chunk(nc, nc % STAGES);
        CP_COMMIT();

        const uint32_t sAh = sb + (ck % STAGES) * STG;
        const uint32_t sBh = sAh + SA;
#pragma unroll
        for (int kk = 0; kk < 2; kk++) {
            uint32_t ahf[2][4], bhf[4][2];
            const uint32_t aoff =
                ((wm + (lane & 15)) * SSTR + kk * 16 + (lane >> 4) * 8) * 2;
#pragma unroll
            for (int mi = 0; mi < 2; mi++)
                LDSM_X4(ahf[mi][0], ahf[mi][1], ahf[mi][2], ahf[mi][3],
                        sAh + aoff + mi * 16 * SSTR * 2);
            const uint32_t boff =
                ((wn + (lane & 7)) * SSTR + kk * 16 + ((lane >> 3) & 1) * 8) * 2;
#pragma unroll
            for (int ni = 0; ni < 4; ni++)
                LDSM_X2(bhf[ni][0], bhf[ni][1], sBh + boff + ni * 8 * SSTR * 2);
#pragma unroll
            for (int mi = 0; mi < 2; mi++)
#pragma unroll
                for (int ni = 0; ni < 4; ni++)
                    mma16816(c[mi][ni], ahf[mi], bhf[ni]);
        }
    }

    // Epilogue: c frag mapping (m16n8): rows lane/4 (+8), cols (lane%4)*2 (+1)
    const int grp = lane >> 2;
    const int tg = (lane & 3) * 2;
#pragma unroll
    for (int mi = 0; mi < 2; mi++)
#pragma unroll
        for (int ni = 0; ni < 4; ni++) {
            float v[4] = {c[mi][ni][0], c[mi][ni][1], c[mi][ni][2], c[mi][ni][3]};
            if (relu) {
#pragma unroll
                for (int i = 0; i < 4; i++) v[i] = fmaxf(v[i], 0.f);
            }
            const size_t r0 = (size_t)(bm + wm + mi * 16 + grp) * Nn + bn + wn + ni * 8 + tg;
            const size_t r1 = r0 + (size_t)8 * Nn;
            if (Y) {
                *(float2*)(Y + r0) = make_float2(v[0], v[1]);
                *(float2*)(Y + r1) = make_float2(v[2], v[3]);
            }
            if (Yh) {
                __half h[4] = {__float2half_rn(v[0]), __float2half_rn(v[1]),
                               __float2half_rn(v[2]), __float2half_rn(v[3])};
                *(uint32_t*)(Yh + r0) = *(uint32_t*)&h[0];
                *(uint32_t*)(Yh + r1) = *(uint32_t*)&h[2];
            }
        }
}

// ---------------------------------------------------------------------------
// Stage B (warp-per-head, 32-row chunks, grid 1024); reads merged kv buffer
// (row stride 512: key at col c, value at col 256+c).
// ---------------------------------------------------------------------------
__global__ void __launch_bounds__(256) stageB_kernel(
    const float* __restrict__ kvbuf,
    const float* __restrict__ spe, const float* __restrict__ smask,
    float* __restrict__ Kpart, float* __restrict__ KVpart)
{
    const int n = blockIdx.x / SUBC;
    const int chunk = blockIdx.x % SUBC;
    const int s0 = chunk * 32;
    const int h = threadIdx.x >> 5;
    const int lane = threadIdx.x & 31;
    const int c = h * 32 + lane;

    float acc[32];
#pragma unroll
    for (int d = 0; d < 32; d++) acc[d] = 0.f;
    float accKs = 0.f;

    const size_t pebase = ((size_t)n * SSEQ + s0) * CC;
    const size_t kvbase = ((size_t)n * SSEQ + s0) * (2*CC);
    const float* mrow = smask + (size_t)n * SSEQ + s0;
    for (int r = 0; r < 32; r++) {
        const size_t kvrow = kvbase + (size_t)r * (2*CC);
        float kc = kvbuf[kvrow + c];
        float vc = kvbuf[kvrow + CC + c];
        float2 pe = *(const float2*)(spe + (pebase + (size_t)r * CC + c) * 2);
        float m  = mrow[r];
        float kp = __shfl_xor_sync(0xffffffffu, kc, 1);
        float vp = __shfl_xor_sync(0xffffffffu, vc, 1);
        float k2 = (lane & 1) ? kp : -kp;
        float v2 = (lane & 1) ? vp : -vp;
        float Kf   = (kc > 0.f ? kc + 1.f : expf(kc)) * m;
        float Kpos = (kc * pe.x + k2 * pe.y) * m;
        float Vr   = (vc * pe.x + v2 * pe.y) * m;
        accKs += Kf;
#pragma unroll
        for (int d = 0; d < 32; d++) {
            float a = __shfl_sync(0xffffffffu, Kpos, d);
            acc[d] = fmaf(a, Vr, acc[d]);
        }
    }
    Kpart[(size_t)(n*SUBC + chunk)*CC + c] = accKs;
    const size_t kvb = (size_t)(n*SUBC + chunk)*KVSZ + h*1024;
#pragma unroll
    for (int d = 0; d < 32; d++)
        KVpart[kvb + d*32 + lane] = acc[d];
}

// Fixed-order reduction of chunk partials -> Ksum, KV (deterministic)
__global__ void __launch_bounds__(256) reduce_parts(
    const float* __restrict__ Kpart, const float* __restrict__ KVpart,
    float* __restrict__ Ksum, float* __restrict__ KV)
{
    int idx = blockIdx.x * 256 + threadIdx.x;
    if (idx < NB*CC) {
        int n = idx / CC, c = idx % CC;
        float s = 0.f;
        for (int ch = 0; ch < SUBC; ch++)
            s += Kpart[(size_t)(n*SUBC + ch)*CC + c];
        Ksum[idx] = s;
        return;
    }
    int kidx = idx - NB*CC;
    if (kidx < NB*KVSZ) {
        int n = kidx / KVSZ, e = kidx % KVSZ;
        float s = 0.f;
        for (int ch = 0; ch < SUBC; ch++)
            s += KVpart[(size_t)(n*SUBC + ch)*KVSZ + e];
        KV[kidx] = s;
    }
}

// ---------------------------------------------------------------------------
// Stage C (warp-per-head): writes queried directly as fp16
// ---------------------------------------------------------------------------
__global__ void __launch_bounds__(256) stageC_kernel(
    const float* __restrict__ query, const float* __restrict__ xpe,
    const float* __restrict__ xmask, const float* __restrict__ Ksum,
    const float* __restrict__ KV, __half* __restrict__ qh)
{
    const int n = blockIdx.x / SUBC;
    const int l0 = (blockIdx.x % SUBC) * 32;
    const int h = threadIdx.x >> 5;
    const int lane = threadIdx.x & 31;
    const int c = h * 32 + lane;

    float kvreg[32];
#pragma unroll
    for (int d = 0; d < 32; d++)
        kvreg[d] = KV[(size_t)n*KVSZ + h*1024 + d*32 + lane];
    const float ks = Ksum[n*CC + c];

    const size_t base = ((size_t)n * LQ + l0) * CC;
    const float* mrow = xmask + (size_t)n * LQ + l0;
    for (int r = 0; r < 32; r++) {
        const size_t row = base + (size_t)r * CC;
        float q  = query[row + c];
        float2 pe = *(const float2*)(xpe + (row + c) * 2);
        float m  = mrow[r];
        float qp = __shfl_xor_sync(0xffffffffu, q, 1);
        float q2 = (lane & 1) ? qp : -qp;
        float Qf   = (q > 0.f ? q + 1.f : expf(q)) * m;
        float Qpos = (q * pe.x + q2 * pe.y) * m;

        float p = Qf * ks;
#pragma unroll
        for (int o = 16; o; o >>= 1) p += __shfl_xor_sync(0xffffffffu, p, o);
        float z = 1.f / (p + 1e-6f);

        float out = 0.f;
#pragma unroll
        for (int d = 0; d < 32; d++) {
            float a = __shfl_sync(0xffffffffu, Qpos, d);
            out = fmaf(a, kvreg[d], out);
        }
        qh[row + c] = __float2half_rn(out * z);
    }
}

// ---------------------------------------------------------------------------
// LayerNorm over last dim (256); one warp per row.
// Writes fp32 (with optional residual) and/or fp16.
// ---------------------------------------------------------------------------
__global__ void __launch_bounds__(256) ln_kernel(
    const float* __restrict__ in, const float* __restrict__ g,
    const float* __restrict__ b, const float* __restrict__ resid,
    float* __restrict__ out, __half* __restrict__ outh)
{
    const int row = blockIdx.x * 8 + (threadIdx.x >> 5);
    const int lane = threadIdx.x & 31;
    const float* p = in + (size_t)row * CC;
    float v[8];
    float s = 0.f;
#pragma unroll
    for (int i = 0; i < 8; i++) { v[i] = p[lane + i*32]; s += v[i]; }
#pragma unroll
    for (int o = 16; o; o >>= 1) s += __shfl_xor_sync(0xffffffffu, s, o);
    float mean = s * (1.f/256.f);
    float s2 = 0.f;
#pragma unroll
    for (int i = 0; i < 8; i++) { float d = v[i] - mean; s2 += d*d; }
#pragma unroll
    for (int o = 16; o; o >>= 1) s2 += __shfl_xor_sync(0xffffffffu, s2, o);
    float rstd = rsqrtf(s2 * (1.f/256.f) + 1e-5f);
#pragma unroll
    for (int i = 0; i < 8; i++) {
        int cch = lane + i*32;
        float o = (v[i] - mean) * rstd * g[cch] + b[cch];
        if (out) {
            float ov = o;
            if (resid) ov += resid[(size_t)row * CC + cch];
            out[(size_t)row * CC + cch] = ov;
        }
        if (outh)
            outh[(size_t)row * CC + cch] = __float2half_rn(o);
    }
}

// ---------------------------------------------------------------------------
extern "C" void kernel_launch(void* const* d_in, const int* in_sizes, int n_in,
                              void* d_out, int out_size)
{
    const float* x     = (const float*)d_in[0];
    const float* src   = (const float*)d_in[1];
    const float* xpe   = (const float*)d_in[2];
    const float* spe   = (const float*)d_in[3];
    const float* xmask = (const float*)d_in[4];
    const float* smask = (const float*)d_in[5];
    const float* Wq    = (const float*)d_in[6];
    const float* Wk    = (const float*)d_in[7];
    const float* Wv    = (const float*)d_in[8];
    const float* Wm    = (const float*)d_in[9];
    const float* W1    = (const float*)d_in[10];
    const float* W2    = (const float*)d_in[11];
    const float* g1    = (const float*)d_in[12];
    const float* b1    = (const float*)d_in[13];
    const float* g2    = (const float*)d_in[14];
    const float* b2    = (const float*)d_in[15];
    float* out = (float*)d_out;

    float *query, *kvbuf, *Kpart, *KVpart, *Ksum, *KV, *msg, *h2;
    __half *xh, *sh, *qh, *m1h, *hbh, *wh;
    cudaGetSymbolAddress((void**)&query,  g_query);
    cudaGetSymbolAddress((void**)&kvbuf,  g_kv);
    cudaGetSymbolAddress((void**)&Kpart,  g_Kpart);
    cudaGetSymbolAddress((void**)&KVpart, g_KVpart);
    cudaGetSymbolAddress((void**)&Ksum,   g_Ksum);
    cudaGetSymbolAddress((void**)&KV,     g_KV);
    cudaGetSymbolAddress((void**)&msg,    g_msg);
    cudaGetSymbolAddress((void**)&h2,     g_h2);
    cudaGetSymbolAddress((void**)&xh,  g_xh);
    cudaGetSymbolAddress((void**)&sh,  g_sh);
    cudaGetSymbolAddress((void**)&qh,  g_qh);
    cudaGetSymbolAddress((void**)&m1h, g_m1h);
    cudaGetSymbolAddress((void**)&hbh, g_hbh);
    cudaGetSymbolAddress((void**)&wh,  g_wh);

    cudaFuncSetAttribute(hgemm<8,false>,  cudaFuncAttributeMaxDynamicSharedMemorySize, SMEM_DYN);
    cudaFuncSetAttribute(hgemm<16,true>,  cudaFuncAttributeMaxDynamicSharedMemorySize, SMEM_DYN);
    cudaFuncSetAttribute(hgemm<16,false>, cudaFuncAttributeMaxDynamicSharedMemorySize, SMEM_DYN);

    dim3 gQ(CC / BN, MTOT / BM);            // (2, 512) N=256
    dim3 gKV(2*CC / BN, MSRC / BM);         // (4, 512) merged N=512
    dim3 gW1(2*CC / BN, MTOT / BM);         // (4, 512)

    // One-time converts
    convert_w<<<WH_TOT/4/256, 256>>>(Wq, Wk, Wv, Wm, W1, W2, wh);
    convert_act<<<MTOT*CC/4/256, 256>>>(x,   xh, MTOT*CC/4);
    convert_act<<<MSRC*CC/4/256, 256>>>(src, sh, MSRC*CC/4);

    // Q projection; merged K|V projection (weight arena rows 0..511 = Wk|Wv)
    hgemm<8,false><<<gQ, 256, SMEM_DYN>>>(xh, xh, 1<<30, CC, wh + WH_Q,
                                          query, nullptr, CC, 0);
    hgemm<8,false><<<gKV, 256, SMEM_DYN>>>(sh, sh, 1<<30, CC, wh + WH_K,
                                           kvbuf, nullptr, 2*CC, 0);

    // Linear-attention KV / Ksum (deterministic two-stage reduction)
    stageB_kernel<<<NB*SUBC, 256>>>(kvbuf, spe, smask, Kpart, KVpart);
    reduce_parts<<<(NB*CC + NB*KVSZ + 255) / 256, 256>>>(Kpart, KVpart, Ksum, KV);

    // Q-side: Z + queried (fp16 out)
    stageC_kernel<<<NB*SUBC, 256>>>(query, xpe, xmask, Ksum, KV, qh);

    // Message projection + LN1 (m1 as fp16)
    hgemm<8,false><<<gQ, 256, SMEM_DYN>>>(qh, qh, 1<<30, CC, wh + WH_M,
                                          msg, nullptr, CC, 0);
    ln_kernel<<<MTOT/8, 256>>>(msg, g1, b1, nullptr, nullptr, m1h);

    // MLP: h = relu([x, m1] @ W1^T) -> fp16; h2 = h @ W2^T -> fp32
    hgemm<16,true><<<gW1, 256, SMEM_DYN>>>(xh, m1h, CC, CC, wh + WH_1,
                                           nullptr, hbh, 2*CC, 1);
    hgemm<16,false><<<gQ, 256, SMEM_DYN>>>(hbh, hbh, 1<<30, 2*CC, wh + WH_2,
                                           h2, nullptr, CC, 0);

    // out = x + LN2(h2)
    ln_kernel<<<MTOT/8, 256>>>(h2, g2, b2, x, out, nullptr);
}

// round 12
// speedup vs baseline: 5.1047x; 1.0786x over previous
#include <cuda_runtime.h>
#include <cuda_fp16.h>
#include <math.h>
#include <stdint.h>

// Problem constants
#define NB 4
#define LQ 8192
#define SSEQ 8192
#define CC 256
#define HH 8
#define DD 32
#define MTOT (NB*LQ)     // 32768 query rows
#define MSRC (NB*SSEQ)   // 32768 source rows
#define SUBC 256         // 32-row chunks per batch
#define KVSZ (HH*DD*DD)  // 8192 per batch

// fp16 weight arena segment offsets (halves)
#define WH_Q  0
#define WH_K  65536      // Wk rows 0..255 then Wv rows 256..511 (contiguous => merged)
#define WH_M  196608
#define WH_1  262144
#define WH_2  524288
#define WH_TOT 655360

// Scratch (device globals: no allocation allowed)
__device__ float g_query[MTOT*CC];
__device__ float g_kv[(size_t)MSRC*2*CC];     // merged key|value, row stride 512
__device__ float g_Kpart[(size_t)NB*SUBC*CC];
__device__ float g_KVpart[(size_t)NB*SUBC*KVSZ];
__device__ float g_Ksum[NB*CC];
__device__ float g_KV[NB*KVSZ];
__device__ float g_msg[MTOT*CC];
__device__ float g_h2[MTOT*CC];
// fp16 activation tensors (single-term)
__device__ __half g_xh[MTOT*CC];
__device__ __half g_sh[MSRC*CC];
__device__ __half g_qh[MTOT*CC];       // queried
__device__ __half g_m1h[MTOT*CC];
__device__ __half g_hbh[(size_t)MTOT*2*CC];
__device__ __half g_wh[WH_TOT];

// ===========================================================================
// Helpers
// ===========================================================================
__device__ __forceinline__ uint32_t smem_u32(const void* p) {
    uint32_t a;
    asm("{ .reg .u64 t; cvta.to.shared.u64 t, %1; cvt.u32.u64 %0, t; }"
        : "=r"(a) : "l"(p));
    return a;
}

#define CP_ASYNC16(dst_u32, src_ptr) \
    asm volatile("cp.async.cg.shared.global [%0], [%1], 16;" \
        :: "r"(dst_u32), "l"(src_ptr))
#define CP_COMMIT() asm volatile("cp.async.commit_group;")
#define CP_WAIT1()  asm volatile("cp.async.wait_group 1;")

#define LDSM_X4(r0,r1,r2,r3, addr) \
    asm volatile("ldmatrix.sync.aligned.m8n8.x4.shared.b16 {%0,%1,%2,%3}, [%4];" \
        : "=r"(r0), "=r"(r1), "=r"(r2), "=r"(r3) : "r"(addr))

__device__ __forceinline__ void mma16816(float* c, const uint32_t* a, const uint32_t* b) {
    asm volatile(
        "mma.sync.aligned.m16n8k16.row.col.f32.f16.f16.f32 "
        "{%0,%1,%2,%3}, {%4,%5,%6,%7}, {%8,%9}, {%0,%1,%2,%3};"
        : "+f"(c[0]), "+f"(c[1]), "+f"(c[2]), "+f"(c[3])
        : "r"(a[0]), "r"(a[1]), "r"(a[2]), "r"(a[3]), "r"(b[0]), "r"(b[1]));
}

// ===========================================================================
// One-time converts (round-to-nearest fp16)
// ===========================================================================
__global__ void convert_act(const float* __restrict__ in,
                            __half* __restrict__ hi, int n4)
{
    int i = blockIdx.x * 256 + threadIdx.x;
    if (i >= n4) return;
    float4 v = ((const float4*)in)[i];
    __half h[4] = {__float2half_rn(v.x), __float2half_rn(v.y),
                   __float2half_rn(v.z), __float2half_rn(v.w)};
    ((uint2*)hi)[i] = *(uint2*)h;
}

__global__ void convert_w(const float* __restrict__ Wq, const float* __restrict__ Wk,
                          const float* __restrict__ Wv, const float* __restrict__ Wm,
                          const float* __restrict__ W1, const float* __restrict__ W2,
                          __half* __restrict__ arena)
{
    int idx = (blockIdx.x * 256 + threadIdx.x) * 4;
    if (idx >= WH_TOT) return;
    const float* src; int off;
    if (idx < WH_1) {
        int seg = idx >> 16;
        src = (seg == 0) ? Wq : (seg == 1) ? Wk : (seg == 2) ? Wv : Wm;
        off = idx & 65535;
    } else if (idx < WH_2) { src = W1; off = idx - WH_1; }
    else                   { src = W2; off = idx - WH_2; }
    float4 v = *(const float4*)(src + off);
    __half h[4] = {__float2half_rn(v.x), __float2half_rn(v.y),
                   __float2half_rn(v.z), __float2half_rn(v.w)};
    *(uint2*)(arena + idx) = *(uint2*)h;
}

// ===========================================================================
// Tensor-core GEMM, cp.async 3-stage pipeline, single-term fp16:
//   Y[m,n] = act( sum_k Ah[m,k] * Bh[n,k] )
// Tile 128x128xBK32, 256 threads / 8 warps, warp tile 64x32, 2 CTAs/SM.
// B fragments loaded 2-ni-at-a-time via ldmatrix.x4.
// Template NK = K/32 (fully unrolls), SPLIT = concat-A (W1 GEMM).
// ===========================================================================
#define BM 128
#define BN 128
#define BK 32
#define STAGES 3
#define SSTR 40                 // padded fp16 row stride (80B): conflict-free ldmatrix
#define SA (128*SSTR*2)         // 10240 B (A tile)
#define SB (128*SSTR*2)         // 10240 B (B tile)
#define STG (SA + SB)           // 20480
#define SMEM_DYN (STAGES*STG)   // 61440

template<int NK, bool SPLIT>
__global__ void __launch_bounds__(256, 2) hgemm(
    const __half* __restrict__ Ah, const __half* __restrict__ A2h,
    int Ksplit, int lda, const __half* __restrict__ W,
    float* __restrict__ Y, __half* __restrict__ Yh,
    int Nn, int relu)
{
    constexpr int K = NK * BK;
    extern __shared__ __align__(16) char smem[];
    const uint32_t sb = smem_u32(smem);

    const int tid = threadIdx.x;
    const int lane = tid & 31;
    const int wid = tid >> 5;
    const int bm = blockIdx.y * BM;
    const int bn = blockIdx.x * BN;
    const int wm = (wid >> 2) * 64;   // 0/64
    const int wn = (wid & 3) * 32;    // 0..96

    // loader mapping: each thread cp.asyncs 16B at rows arow and arow+64
    const int arow = tid >> 2;          // 0..63
    const int acol = (tid & 3) * 8;     // 0,8,16,24
    const uint32_t sOff0 = (uint32_t)(arow * SSTR + acol) * 2;
    const uint32_t sOff1 = sOff0 + (uint32_t)(64 * SSTR * 2);

    // issue loads for chunk ck into stage st
    auto load_chunk = [&](int ck, int st) {
        const int k0 = ck * BK;
        const __half* ah = Ah;
        int kk0 = k0;
        if (SPLIT && k0 >= Ksplit) { ah = A2h; kk0 = k0 - Ksplit; }
        const uint32_t base = sb + st * STG;
        CP_ASYNC16(base + sOff0, ah + (size_t)(bm + arow) * lda + kk0 + acol);
        CP_ASYNC16(base + sOff1, ah + (size_t)(bm + 64 + arow) * lda + kk0 + acol);
        CP_ASYNC16(base + SA + sOff0, W + (size_t)(bn + arow) * K + k0 + acol);
        CP_ASYNC16(base + SA + sOff1, W + (size_t)(bn + 64 + arow) * K + k0 + acol);
    };

    float c[4][4][4];
#pragma unroll
    for (int mi = 0; mi < 4; mi++)
#pragma unroll
        for (int ni = 0; ni < 4; ni++)
#pragma unroll
            for (int i = 0; i < 4; i++) c[mi][ni][i] = 0.f;

    load_chunk(0, 0); CP_COMMIT();
    load_chunk(1, 1); CP_COMMIT();

#pragma unroll
    for (int ck = 0; ck < NK; ck++) {
        CP_WAIT1();
        __syncthreads();   // orders mma(ck-1) of all warps before that slot is refilled

        const int nc = ck + STAGES - 1;
        if (nc < NK) load_chunk(nc, nc % STAGES);
        CP_COMMIT();

        const uint32_t sAh = sb + (ck % STAGES) * STG;
        const uint32_t sBh = sAh + SA;
#pragma unroll
        for (int kk = 0; kk < 2; kk++) {
            uint32_t ahf[4][4], bhf[4][2];
            // A frags: 4 x ldmatrix.x4 (rows wm+mi*16+(lane&15), k kk*16+(lane>>4)*8)
            const uint32_t aoff =
                ((wm + (lane & 15)) * SSTR + kk * 16 + (lane >> 4) * 8) * 2;
#pragma unroll
            for (int mi = 0; mi < 4; mi++)
                LDSM_X4(ahf[mi][0], ahf[mi][1], ahf[mi][2], ahf[mi][3],
                        sAh + aoff + mi * 16 * SSTR * 2);
            // B frags: 2 x ldmatrix.x4, each covers ni pair (2p, 2p+1):
            //   n row = wn + p*16 + (lane>>4)*8 + (lane&7); k = kk*16 + ((lane>>3)&1)*8
            const uint32_t boff =
                ((wn + (lane >> 4) * 8 + (lane & 7)) * SSTR
                 + kk * 16 + ((lane >> 3) & 1) * 8) * 2;
#pragma unroll
            for (int p = 0; p < 2; p++)
                LDSM_X4(bhf[2*p][0], bhf[2*p][1], bhf[2*p+1][0], bhf[2*p+1][1],
                        sBh + boff + p * 16 * SSTR * 2);
#pragma unroll
            for (int mi = 0; mi < 4; mi++)
#pragma unroll
                for (int ni = 0; ni < 4; ni++)
                    mma16816(c[mi][ni], ahf[mi], bhf[ni]);
        }
    }

    // Epilogue: c frag mapping (m16n8): rows lane/4 (+8), cols (lane%4)*2 (+1)
    const int grp = lane >> 2;
    const int tg = (lane & 3) * 2;
#pragma unroll
    for (int mi = 0; mi < 4; mi++)
#pragma unroll
        for (int ni = 0; ni < 4; ni++) {
            float v[4] = {c[mi][ni][0], c[mi][ni][1], c[mi][ni][2], c[mi][ni][3]};
            if (relu) {
#pragma unroll
                for (int i = 0; i < 4; i++) v[i] = fmaxf(v[i], 0.f);
            }
            const size_t r0 = (size_t)(bm + wm + mi * 16 + grp) * Nn + bn + wn + ni * 8 + tg;
            const size_t r1 = r0 + (size_t)8 * Nn;
            if (Y) {
                *(float2*)(Y + r0) = make_float2(v[0], v[1]);
                *(float2*)(Y + r1) = make_float2(v[2], v[3]);
            }
            if (Yh) {
                __half h[4] = {__float2half_rn(v[0]), __float2half_rn(v[1]),
                               __float2half_rn(v[2]), __float2half_rn(v[3])};
                *(uint32_t*)(Yh + r0) = *(uint32_t*)&h[0];
                *(uint32_t*)(Yh + r1) = *(uint32_t*)&h[2];
            }
        }
}

// ---------------------------------------------------------------------------
// Stage B (warp-per-head, 32-row chunks, grid 1024); reads merged kv buffer
// (row stride 512: key at col c, value at col 256+c).
// ---------------------------------------------------------------------------
__global__ void __launch_bounds__(256) stageB_kernel(
    const float* __restrict__ kvbuf,
    const float* __restrict__ spe, const float* __restrict__ smask,
    float* __restrict__ Kpart, float* __restrict__ KVpart)
{
    const int n = blockIdx.x / SUBC;
    const int chunk = blockIdx.x % SUBC;
    const int s0 = chunk * 32;
    const int h = threadIdx.x >> 5;
    const int lane = threadIdx.x & 31;
    const int c = h * 32 + lane;

    float acc[32];
#pragma unroll
    for (int d = 0; d < 32; d++) acc[d] = 0.f;
    float accKs = 0.f;

    const size_t pebase = ((size_t)n * SSEQ + s0) * CC;
    const size_t kvbase = ((size_t)n * SSEQ + s0) * (2*CC);
    const float* mrow = smask + (size_t)n * SSEQ + s0;
    for (int r = 0; r < 32; r++) {
        const size_t kvrow = kvbase + (size_t)r * (2*CC);
        float kc = kvbuf[kvrow + c];
        float vc = kvbuf[kvrow + CC + c];
        float2 pe = *(const float2*)(spe + (pebase + (size_t)r * CC + c) * 2);
        float m  = mrow[r];
        float kp = __shfl_xor_sync(0xffffffffu, kc, 1);
        float vp = __shfl_xor_sync(0xffffffffu, vc, 1);
        float k2 = (lane & 1) ? kp : -kp;
        float v2 = (lane & 1) ? vp : -vp;
        float Kf   = (kc > 0.f ? kc + 1.f : expf(kc)) * m;
        float Kpos = (kc * pe.x + k2 * pe.y) * m;
        float Vr   = (vc * pe.x + v2 * pe.y) * m;
        accKs += Kf;
#pragma unroll
        for (int d = 0; d < 32; d++) {
            float a = __shfl_sync(0xffffffffu, Kpos, d);
            acc[d] = fmaf(a, Vr, acc[d]);
        }
    }
    Kpart[(size_t)(n*SUBC + chunk)*CC + c] = accKs;
    const size_t kvb = (size_t)(n*SUBC + chunk)*KVSZ + h*1024;
#pragma unroll
    for (int d = 0; d < 32; d++)
        KVpart[kvb + d*32 + lane] = acc[d];
}

// Fixed-order reduction of chunk partials -> Ksum, KV (deterministic)
__global__ void __launch_bounds__(256) reduce_parts(
    const float* __restrict__ Kpart, const float* __restrict__ KVpart,
    float* __restrict__ Ksum, float* __restrict__ KV)
{
    int idx = blockIdx.x * 256 + threadIdx.x;
    if (idx < NB*CC) {
        int n = idx / CC, c = idx % CC;
        float s = 0.f;
        for (int ch = 0; ch < SUBC; ch++)
            s += Kpart[(size_t)(n*SUBC + ch)*CC + c];
        Ksum[idx] = s;
        return;
    }
    int kidx = idx - NB*CC;
    if (kidx < NB*KVSZ) {
        int n = kidx / KVSZ, e = kidx % KVSZ;
        float s = 0.f;
        for (int ch = 0; ch < SUBC; ch++)
            s += KVpart[(size_t)(n*SUBC + ch)*KVSZ + e];
        KV[kidx] = s;
    }
}

// ---------------------------------------------------------------------------
// Stage C (warp-per-head): writes queried directly as fp16
// ---------------------------------------------------------------------------
__global__ void __launch_bounds__(256) stageC_kernel(
    const float* __restrict__ query, const float* __restrict__ xpe,
    const float* __restrict__ xmask, const float* __restrict__ Ksum,
    const float* __restrict__ KV, __half* __restrict__ qh)
{
    const int n = blockIdx.x / SUBC;
    const int l0 = (blockIdx.x % SUBC) * 32;
    const int h = threadIdx.x >> 5;
    const int lane = threadIdx.x & 31;
    const int c = h * 32 + lane;

    float kvreg[32];
#pragma unroll
    for (int d = 0; d < 32; d++)
        kvreg[d] = KV[(size_t)n*KVSZ + h*1024 + d*32 + lane];
    const float ks = Ksum[n*CC + c];

    const size_t base = ((size_t)n * LQ + l0) * CC;
    const float* mrow = xmask + (size_t)n * LQ + l0;
    for (int r = 0; r < 32; r++) {
        const size_t row = base + (size_t)r * CC;
        float q  = query[row + c];
        float2 pe = *(const float2*)(xpe + (row + c) * 2);
        float m  = mrow[r];
        float qp = __shfl_xor_sync(0xffffffffu, q, 1);
        float q2 = (lane & 1) ? qp : -qp;
        float Qf   = (q > 0.f ? q + 1.f : expf(q)) * m;
        float Qpos = (q * pe.x + q2 * pe.y) * m;

        float p = Qf * ks;
#pragma unroll
        for (int o = 16; o; o >>= 1) p += __shfl_xor_sync(0xffffffffu, p, o);
        float z = 1.f / (p + 1e-6f);

        float out = 0.f;
#pragma unroll
        for (int d = 0; d < 32; d++) {
            float a = __shfl_sync(0xffffffffu, Qpos, d);
            out = fmaf(a, kvreg[d], out);
        }
        qh[row + c] = __float2half_rn(out * z);
    }
}

// ---------------------------------------------------------------------------
// LayerNorm over last dim (256); one warp per row.
// Writes fp32 (with optional residual) and/or fp16.
// ---------------------------------------------------------------------------
__global__ void __launch_bounds__(256) ln_kernel(
    const float* __restrict__ in, const float* __restrict__ g,
    const float* __restrict__ b, const float* __restrict__ resid,
    float* __restrict__ out, __half* __restrict__ outh)
{
    const int row = blockIdx.x * 8 + (threadIdx.x >> 5);
    const int lane = threadIdx.x & 31;
    const float* p = in + (size_t)row * CC;
    float v[8];
    float s = 0.f;
#pragma unroll
    for (int i = 0; i < 8; i++) { v[i] = p[lane + i*32]; s += v[i]; }
#pragma unroll
    for (int o = 16; o; o >>= 1) s += __shfl_xor_sync(0xffffffffu, s, o);
    float mean = s * (1.f/256.f);
    float s2 = 0.f;
#pragma unroll
    for (int i = 0; i < 8; i++) { float d = v[i] - mean; s2 += d*d; }
#pragma unroll
    for (int o = 16; o; o >>= 1) s2 += __shfl_xor_sync(0xffffffffu, s2, o);
    float rstd = rsqrtf(s2 * (1.f/256.f) + 1e-5f);
#pragma unroll
    for (int i = 0; i < 8; i++) {
        int cch = lane + i*32;
        float o = (v[i] - mean) * rstd * g[cch] + b[cch];
        if (out) {
            float ov = o;
            if (resid) ov += resid[(size_t)row * CC + cch];
            out[(size_t)row * CC + cch] = ov;
        }
        if (outh)
            outh[(size_t)row * CC + cch] = __float2half_rn(o);
    }
}

// ---------------------------------------------------------------------------
extern "C" void kernel_launch(void* const* d_in, const int* in_sizes, int n_in,
                              void* d_out, int out_size)
{
    const float* x     = (const float*)d_in[0];
    const float* src   = (const float*)d_in[1];
    const float* xpe   = (const float*)d_in[2];
    const float* spe   = (const float*)d_in[3];
    const float* xmask = (const float*)d_in[4];
    const float* smask = (const float*)d_in[5];
    const float* Wq    = (const float*)d_in[6];
    const float* Wk    = (const float*)d_in[7];
    const float* Wv    = (const float*)d_in[8];
    const float* Wm    = (const float*)d_in[9];
    const float* W1    = (const float*)d_in[10];
    const float* W2    = (const float*)d_in[11];
    const float* g1    = (const float*)d_in[12];
    const float* b1    = (const float*)d_in[13];
    const float* g2    = (const float*)d_in[14];
    const float* b2    = (const float*)d_in[15];
    float* out = (float*)d_out;

    float *query, *kvbuf, *Kpart, *KVpart, *Ksum, *KV, *msg, *h2;
    __half *xh, *sh, *qh, *m1h, *hbh, *wh;
    cudaGetSymbolAddress((void**)&query,  g_query);
    cudaGetSymbolAddress((void**)&kvbuf,  g_kv);
    cudaGetSymbolAddress((void**)&Kpart,  g_Kpart);
    cudaGetSymbolAddress((void**)&KVpart, g_KVpart);
    cudaGetSymbolAddress((void**)&Ksum,   g_Ksum);
    cudaGetSymbolAddress((void**)&KV,     g_KV);
    cudaGetSymbolAddress((void**)&msg,    g_msg);
    cudaGetSymbolAddress((void**)&h2,     g_h2);
    cudaGetSymbolAddress((void**)&xh,  g_xh);
    cudaGetSymbolAddress((void**)&sh,  g_sh);
    cudaGetSymbolAddress((void**)&qh,  g_qh);
    cudaGetSymbolAddress((void**)&m1h, g_m1h);
    cudaGetSymbolAddress((void**)&hbh, g_hbh);
    cudaGetSymbolAddress((void**)&wh,  g_wh);

    cudaFuncSetAttribute(hgemm<8,false>,  cudaFuncAttributeMaxDynamicSharedMemorySize, SMEM_DYN);
    cudaFuncSetAttribute(hgemm<16,true>,  cudaFuncAttributeMaxDynamicSharedMemorySize, SMEM_DYN);
    cudaFuncSetAttribute(hgemm<16,false>, cudaFuncAttributeMaxDynamicSharedMemorySize, SMEM_DYN);

    dim3 gQ(CC / BN, MTOT / BM);            // (2, 256) N=256
    dim3 gKV(2*CC / BN, MSRC / BM);         // (4, 256) merged N=512
    dim3 gW1(2*CC / BN, MTOT / BM);         // (4, 256)

    // One-time converts
    convert_w<<<WH_TOT/4/256, 256>>>(Wq, Wk, Wv, Wm, W1, W2, wh);
    convert_act<<<MTOT*CC/4/256, 256>>>(x,   xh, MTOT*CC/4);
    convert_act<<<MSRC*CC/4/256, 256>>>(src, sh, MSRC*CC/4);

    // Q projection; merged K|V projection (weight arena rows 0..511 = Wk|Wv)
    hgemm<8,false><<<gQ, 256, SMEM_DYN>>>(xh, xh, 1<<30, CC, wh + WH_Q,
                                          query, nullptr, CC, 0);
    hgemm<8,false><<<gKV, 256, SMEM_DYN>>>(sh, sh, 1<<30, CC, wh + WH_K,
                                           kvbuf, nullptr, 2*CC, 0);

    // Linear-attention KV / Ksum (deterministic two-stage reduction)
    stageB_kernel<<<NB*SUBC, 256>>>(kvbuf, spe, smask, Kpart, KVpart);
    reduce_parts<<<(NB*CC + NB*KVSZ + 255) / 256, 256>>>(Kpart, KVpart, Ksum, KV);

    // Q-side: Z + queried (fp16 out)
    stageC_kernel<<<NB*SUBC, 256>>>(query, xpe, xmask, Ksum, KV, qh);

    // Message projection + LN1 (m1 as fp16)
    hgemm<8,false><<<gQ, 256, SMEM_DYN>>>(qh, qh, 1<<30, CC, wh + WH_M,
                                          msg, nullptr, CC, 0);
    ln_kernel<<<MTOT/8, 256>>>(msg, g1, b1, nullptr, nullptr, m1h);

    // MLP: h = relu([x, m1] @ W1^T) -> fp16; h2 = h @ W2^T -> fp32
    hgemm<16,true><<<gW1, 256, SMEM_DYN>>>(xh, m1h, CC, CC, wh + WH_1,
                                           nullptr, hbh, 2*CC, 1);
    hgemm<16,false><<<gQ, 256, SMEM_DYN>>>(hbh, hbh, 1<<30, 2*CC, wh + WH_2,
                                           h2, nullptr, CC, 0);

    // out = x + LN2(h2)
    ln_kernel<<<MTOT/8, 256>>>(h2, g2, b2, x, out, nullptr);
}